// round 1
// baseline (speedup 1.0000x reference)
#include <cuda_runtime.h>

#define NN 50
#define DD 128
#define TPB 128
#define EPSV 1e-8f
#define EMAX 1024

struct Smem {
    union {
        float emb[NN][132];                    // staging one graph's embeddings
        float M[2][NN][53];                    // GCN dense adjacency (normalized)
        struct { float h1[2][NN][21]; float h2[2][NN][21]; } hh;
    } big;
    union {
        float Wt[20][DD];                      // [conv_w | cross_w] transposed
        float attn[NN][51];
    } wa;
    float proj[2][NN][21];                     // cols 0..9: emb@conv_w, 10..19: emb@cross_w
    float assign[NN][10];
    float mpw1[11][20];
    float mpw2[20][20];
    float mpb1[20], mpb2[20], convb[10];
    float dinv[2][NN];
    float gmax[2][20];
    float feat[80];
    float z[40];
    int   tok[2][NN];
    unsigned short edge[2][EMAX];              // src | dst<<8
};

__device__ __forceinline__ unsigned long long pk2(float a, float b) {
    union { float2 f; unsigned long long u; } c;
    c.f = make_float2(a, b);
    return c.u;
}
__device__ __forceinline__ float unpk_sum(unsigned long long u) {
    union { float2 f; unsigned long long u; } c;
    c.u = u;
    return c.f.x + c.f.y;
}
#define FMA2(d, a, b) asm("fma.rn.f32x2 %0, %1, %2, %0;" : "+l"(d) : "l"(a), "l"(b))

__global__ void __launch_bounds__(TPB, 4) gmn_kernel(
    const int* __restrict__ utok, const int* __restrict__ rtok,
    const int* __restrict__ uadj, const int* __restrict__ radj,
    const float* __restrict__ emb,
    const float* __restrict__ conv_w, const float* __restrict__ conv_b,
    const float* __restrict__ cross_w, const float* __restrict__ attn,
    const float* __restrict__ assignw,
    const float* __restrict__ mpw1, const float* __restrict__ mpb1,
    const float* __restrict__ mpw2, const float* __restrict__ mpb2,
    const float* __restrict__ fw1, const float* __restrict__ fb1,
    const float* __restrict__ fw2, const float* __restrict__ fb2,
    float* __restrict__ out, int E)
{
    extern __shared__ char smraw[];
    Smem& s = *reinterpret_cast<Smem*>(smraw);
    const int t = threadIdx.x;
    const int b = blockIdx.x;

    // ---------------- Phase 0: cooperative loads ----------------
    for (int i = t; i < 2 * NN; i += TPB) {
        int g = i / NN, n = i - (i / NN) * NN;
        s.tok[g][n] = (g == 0 ? utok : rtok)[b * NN + n];
        s.dinv[g][n] = 1.0f;                    // self-loop degree seed
    }
    for (int i = t; i < 2 * E; i += TPB) {
        int g = i / E, e = i - g * E;
        const int* adj = (g == 0 ? uadj : radj) + (size_t)b * 2 * E;
        int sr = adj[e], ds = adj[E + e];
        s.edge[g][e] = (unsigned short)(sr | (ds << 8));
    }
    for (int i = t; i < 20 * DD; i += TPB) {
        int j = i >> 7, d = i & (DD - 1);
        s.wa.Wt[j][d] = (j < 10) ? conv_w[d * 10 + j] : cross_w[d * 10 + (j - 10)];
    }
    for (int i = t; i < NN * 10; i += TPB) s.assign[i / 10][i % 10] = assignw[i];
    for (int i = t; i < 11 * 20; i += TPB) s.mpw1[i / 20][i % 20] = mpw1[i];
    for (int i = t; i < 20 * 20; i += TPB) s.mpw2[i / 20][i % 20] = mpw2[i];
    if (t < 20) { s.mpb1[t] = mpb1[t]; s.mpb2[t] = mpb2[t]; }
    if (t < 10) s.convb[t] = conv_b[t];
    __syncthreads();

    // degree accumulation (counts dst occurrences; completes well before use)
    for (int i = t; i < 2 * E; i += TPB) {
        int g = i / E, e = i - g * E;
        atomicAdd(&s.dinv[g][(s.edge[g][e] >> 8)], 1.0f);
    }

    // ---------------- Phase 1: projections proj = emb @ [conv_w|cross_w] ----------------
    const int pr = t >> 1, ph = t & 1;   // (row, dim-half) split: 100 active threads
    for (int g = 0; g < 2; g++) {
        for (int i = t; i < NN * 32; i += TPB) {
            int row = i >> 5, seg = i & 31;
            const float4* sp = reinterpret_cast<const float4*>(emb + (size_t)s.tok[g][row] * DD);
            *reinterpret_cast<float4*>(&s.big.emb[row][seg * 4]) = sp[seg];
        }
        __syncthreads();
        float sums[20];
        if (t < 100) {
            unsigned long long acc[20];
#pragma unroll
            for (int j = 0; j < 20; j++) acc[j] = 0ull;
            const float* er = &s.big.emb[pr][ph * 64];
#pragma unroll 4
            for (int c = 0; c < 64; c += 4) {
                float4 e4 = *reinterpret_cast<const float4*>(er + c);
                unsigned long long e01 = pk2(e4.x, e4.y);
                unsigned long long e23 = pk2(e4.z, e4.w);
#pragma unroll
                for (int j = 0; j < 20; j++) {
                    float4 w4 = *reinterpret_cast<const float4*>(&s.wa.Wt[j][ph * 64 + c]);
                    unsigned long long w01 = pk2(w4.x, w4.y);
                    unsigned long long w23 = pk2(w4.z, w4.w);
                    FMA2(acc[j], e01, w01);
                    FMA2(acc[j], e23, w23);
                }
            }
#pragma unroll
            for (int j = 0; j < 20; j++) sums[j] = unpk_sum(acc[j]);
        }
        __syncthreads();   // emb reads done; proj write order below
        if (t < 100 && ph == 0) {
#pragma unroll
            for (int j = 0; j < 20; j++) s.proj[g][pr][j] = sums[j];
        }
        __syncthreads();
        if (t < 100 && ph == 1) {
#pragma unroll
            for (int j = 0; j < 20; j++) s.proj[g][pr][j] += sums[j];
        }
        __syncthreads();
    }

    // ---------------- Phase 2: build normalized adjacency M (emb buffer is dead) ----------------
    {
        float* mflat = &s.big.M[0][0][0];
        for (int i = t; i < 2 * NN * 53; i += TPB) mflat[i] = 0.0f;
    }
    for (int i = t; i < 2 * NN; i += TPB) {
        int g = i / NN, n = i - (i / NN) * NN;
        s.dinv[g][n] = rsqrtf(s.dinv[g][n]);
    }
    for (int i = t; i < NN * NN; i += TPB) s.wa.attn[i / NN][i % NN] = attn[i]; // Wt dead
    __syncthreads();
    for (int i = t; i < 2 * E; i += TPB) {
        int g = i / E, e = i - g * E;
        unsigned v = s.edge[g][e];
        int sr = v & 255, ds = v >> 8;
        atomicAdd(&s.big.M[g][ds][sr], s.dinv[g][sr] * s.dinv[g][ds]);
    }
    __syncthreads();
    if (t < 100) {
        int g = t / NN, n = t - (t / NN) * NN;
        float dn = s.dinv[g][n];
        s.big.M[g][n][n] += dn * dn;          // self loop (post-atomics, unique owner)
    }
    __syncthreads();

    // ---------------- Phase 3: fused GCN-GEMM + cross-GEMM + cosine + MLP1 ----------------
    const int g3 = (t < 100) ? (t / NN) : 0;
    const int n3 = (t < 100) ? (t - g3 * NN) : 0;
    float selfv[10], crossv[10];
    float dist = 0.0f;
    if (t < 100) {
#pragma unroll
        for (int j = 0; j < 10; j++) { selfv[j] = 0.0f; crossv[j] = 0.0f; }
#pragma unroll 2
        for (int m = 0; m < NN; m++) {
            float Mv = s.big.M[g3][n3][m];
            float Av = s.wa.attn[n3][m];
            const float* psrc = s.proj[g3][m];           // xw (cols 0..9)
            const float* pcrs = s.proj[1 - g3][m] + 10;  // other graph's emb@cross_w
#pragma unroll
            for (int j = 0; j < 10; j++) {
                selfv[j] += Mv * psrc[j];
                crossv[j] += Av * pcrs[j];
            }
        }
        float dot = 0.0f, na = 0.0f, nc = 0.0f;
#pragma unroll
        for (int j = 0; j < 10; j++) {
            selfv[j] += s.convb[j];
            float aw = s.assign[n3][j];
            float av = aw * selfv[j], cv = aw * crossv[j];
            dot += av * cv; na += av * av; nc += cv * cv;
        }
        na = fmaxf(sqrtf(na), EPSV);
        nc = fmaxf(sqrtf(nc), EPSV);
        dist = dot / (na * nc);
    }
    __syncthreads();   // M/attn/proj reads done before h1 overwrites the union
    if (t < 100) {
#pragma unroll
        for (int j = 0; j < 20; j++) {
            float a = s.mpb1[j] + dist * s.mpw1[0][j];
#pragma unroll
            for (int k = 0; k < 10; k++) a += selfv[k] * s.mpw1[k + 1][j];
            s.big.hh.h1[g3][n3][j] = fmaxf(a, 0.0f);
        }
    }
    __syncthreads();
    if (t < 100) {
        float h2a[20];
#pragma unroll
        for (int j = 0; j < 20; j++) h2a[j] = s.mpb2[j];
#pragma unroll 4
        for (int k = 0; k < 20; k++) {
            float hk = s.big.hh.h1[g3][n3][k];
#pragma unroll
            for (int j = 0; j < 20; j++) h2a[j] += hk * s.mpw2[k][j];
        }
#pragma unroll
        for (int j = 0; j < 20; j++) s.big.hh.h2[g3][n3][j] = h2a[j];
    }
    __syncthreads();

    // ---------------- Phase 4: node-max, feature build, FFN, sigmoid ----------------
    if (t < 40) {
        int g = t / 20, j = t - g * 20;
        float m = -3.4e38f;
        for (int n = 0; n < NN; n++) m = fmaxf(m, s.big.hh.h2[g][n][j]);
        s.gmax[g][j] = m;
    }
    __syncthreads();
    if (t < 80) {
        int q = t / 20, i = t - q * 20;
        float gu = s.gmax[0][i], gr = s.gmax[1][i];
        float v = (q == 0) ? gu : (q == 1) ? gr : (q == 2) ? gu * gr : fabsf(gu - gr);
        s.feat[t] = v;
    }
    __syncthreads();
    if (t < 40) {
        float a = fb1[t];
        for (int i = 0; i < 80; i++) a += s.feat[i] * fw1[i * 40 + t];
        s.z[t] = fmaxf(a, 0.0f);
    }
    __syncthreads();
    if (t == 0) {
        float lg = fb2[0];
        for (int i = 0; i < 40; i++) lg += s.z[i] * fw2[i];
        out[b] = 1.0f / (1.0f + expf(-lg));
    }
}

extern "C" void kernel_launch(void* const* d_in, const int* in_sizes, int n_in,
                              void* d_out, int out_size) {
    const int* utok   = (const int*)d_in[0];
    const int* rtok   = (const int*)d_in[1];
    const int* uadj   = (const int*)d_in[2];
    const int* radj   = (const int*)d_in[3];
    const float* emb  = (const float*)d_in[4];
    const float* cw   = (const float*)d_in[5];
    const float* cb   = (const float*)d_in[6];
    const float* xw   = (const float*)d_in[7];
    const float* attn = (const float*)d_in[8];
    const float* asw  = (const float*)d_in[9];
    const float* mw1  = (const float*)d_in[10];
    const float* mb1  = (const float*)d_in[11];
    const float* mw2  = (const float*)d_in[12];
    const float* mb2  = (const float*)d_in[13];
    const float* fw1  = (const float*)d_in[14];
    const float* fb1  = (const float*)d_in[15];
    const float* fw2  = (const float*)d_in[16];
    const float* fb2  = (const float*)d_in[17];
    float* out = (float*)d_out;

    int B = in_sizes[0] / NN;
    int E = in_sizes[2] / (2 * B);

    cudaFuncSetAttribute(gmn_kernel, cudaFuncAttributeMaxDynamicSharedMemorySize,
                         (int)sizeof(Smem));
    gmn_kernel<<<B, TPB, sizeof(Smem)>>>(utok, rtok, uadj, radj, emb,
                                         cw, cb, xw, attn, asw,
                                         mw1, mb1, mw2, mb2,
                                         fw1, fb1, fw2, fb2,
                                         out, E);
}

// round 2
// speedup vs baseline: 1.2500x; 1.2500x over previous
#include <cuda_runtime.h>

#define NN 50
#define TPB 128
#define EPSV 1e-8f
#define EMAXE 512

#define EMB_PH 3404        // 50*68 + 4 (ph stride, bank-staggered)
#define EMB_ROW 68

struct Smem {
    union {
        float emb[2 * EMB_PH + 4];                       // 6812 floats
        float M[2][NN][53];                              // 5300
        float h2[2][NN][21];                             // 2100
    } big;
    union {
        float Wt[2][20][EMB_ROW];                        // [ph][j][c]
        float attn[NN][51];
    } wa;
    float proj[2][NN][24];                               // conv at 0..9, cross at 12..21
    float assign[NN][10];
    float mpw1[11][20];
    float mpw2[20][20];
    float mpb1[20], mpb2[20], convb[10];
    float dinv[2][NN];
    float gmax[2][20];
    float feat[80];
    float z[40];
    int   tok[2][NN];
    unsigned short edge[2][EMAXE];
};

__device__ __forceinline__ unsigned long long pk2(float a, float b) {
    union { float2 f; unsigned long long u; } c;
    c.f = make_float2(a, b);
    return c.u;
}
__device__ __forceinline__ float unpk_sum(unsigned long long u) {
    union { float2 f; unsigned long long u; } c;
    c.u = u;
    return c.f.x + c.f.y;
}
#define FMA2(d, a, b) asm("fma.rn.f32x2 %0, %1, %2, %0;" : "+l"(d) : "l"(a), "l"(b))

__global__ void __launch_bounds__(TPB, 4) gmn_kernel(
    const int* __restrict__ utok, const int* __restrict__ rtok,
    const int* __restrict__ uadj, const int* __restrict__ radj,
    const float* __restrict__ emb,
    const float* __restrict__ conv_w, const float* __restrict__ conv_b,
    const float* __restrict__ cross_w, const float* __restrict__ attn,
    const float* __restrict__ assignw,
    const float* __restrict__ mpw1, const float* __restrict__ mpb1,
    const float* __restrict__ mpw2, const float* __restrict__ mpb2,
    const float* __restrict__ fw1, const float* __restrict__ fb1,
    const float* __restrict__ fw2, const float* __restrict__ fb2,
    float* __restrict__ out, int E)
{
    extern __shared__ char smraw[];
    Smem& s = *reinterpret_cast<Smem*>(smraw);
    const int t = threadIdx.x;
    const int b = blockIdx.x;

    // ---------------- Phase 0: cooperative loads ----------------
    for (int i = t; i < 2 * NN; i += TPB) {
        int g = i / NN, n = i - (i / NN) * NN;
        s.tok[g][n] = (g == 0 ? utok : rtok)[b * NN + n];
        s.dinv[g][n] = 1.0f;                    // self-loop seed
    }
    for (int i = t; i < 2 * E; i += TPB) {
        int g = i / E, e = i - g * E;
        const int* adj = (g == 0 ? uadj : radj) + (size_t)b * 2 * E;
        int sr = adj[e], ds = adj[E + e];
        s.edge[g][e] = (unsigned short)(sr | (ds << 8));
    }
    for (int i = t; i < 20 * 128; i += TPB) {
        int j = i >> 7, d = i & 127;
        int phs = d >> 6, c = d & 63;
        s.wa.Wt[phs][j][c] = (j < 10) ? conv_w[d * 10 + j] : cross_w[d * 10 + (j - 10)];
    }
    for (int i = t; i < NN * 10; i += TPB) s.assign[i / 10][i % 10] = assignw[i];
    for (int i = t; i < 11 * 20; i += TPB) s.mpw1[i / 20][i % 20] = mpw1[i];
    for (int i = t; i < 20 * 20; i += TPB) s.mpw2[i / 20][i % 20] = mpw2[i];
    if (t < 20) { s.mpb1[t] = mpb1[t]; s.mpb2[t] = mpb2[t]; }
    if (t < 10) s.convb[t] = conv_b[t];
    __syncthreads();

    // degree accumulation (runs alongside phase-1 staging; done before phase 2)
    for (int i = t; i < 2 * E; i += TPB) {
        int g = i / E, e = i - g * E;
        atomicAdd(&s.dinv[g][(s.edge[g][e] >> 8)], 1.0f);
    }

    // ---------------- Phase 1: proj = emb @ [conv_w | cross_w] ----------------
    // thread = (row-pair rp, dim-half ph, j-half jh): W reused across 2 rows,
    // halves combined via shfl_xor(2).
    const int rp_raw = t >> 2;                  // 0..31
    const int rp = (rp_raw < 25) ? rp_raw : 24; // clamp so all lanes shuffle
    const int ph = (t >> 1) & 1;
    const int jh = t & 1;
    const int r0 = rp * 2, r1 = r0 + 1;

    for (int g = 0; g < 2; g++) {
        for (int i = t; i < NN * 32; i += TPB) {
            int row = i >> 5, seg = i & 31;
            int phs = seg >> 4, c4 = seg & 15;
            const float4* sp = reinterpret_cast<const float4*>(emb + (size_t)s.tok[g][row] * 128);
            *reinterpret_cast<float4*>(&s.big.emb[phs * EMB_PH + row * EMB_ROW + c4 * 4]) = sp[seg];
        }
        __syncthreads();

        unsigned long long a0[10], a1[10];
#pragma unroll
        for (int jj = 0; jj < 10; jj++) { a0[jj] = 0ull; a1[jj] = 0ull; }
        const float* e0p = &s.big.emb[ph * EMB_PH + r0 * EMB_ROW];
        const float* e1p = e0p + EMB_ROW;
        const float* wp  = &s.wa.Wt[ph][jh * 10][0];
#pragma unroll 4
        for (int c4 = 0; c4 < 16; c4++) {
            float4 e0 = *reinterpret_cast<const float4*>(e0p + c4 * 4);
            float4 e1 = *reinterpret_cast<const float4*>(e1p + c4 * 4);
            unsigned long long e0a = pk2(e0.x, e0.y), e0b = pk2(e0.z, e0.w);
            unsigned long long e1a = pk2(e1.x, e1.y), e1b = pk2(e1.z, e1.w);
#pragma unroll
            for (int jj = 0; jj < 10; jj++) {
                float4 w = *reinterpret_cast<const float4*>(wp + jj * EMB_ROW + c4 * 4);
                unsigned long long wa_ = pk2(w.x, w.y), wb_ = pk2(w.z, w.w);
                FMA2(a0[jj], e0a, wa_); FMA2(a0[jj], e0b, wb_);
                FMA2(a1[jj], e1a, wa_); FMA2(a1[jj], e1b, wb_);
            }
        }
        float s0[10], s1[10];
#pragma unroll
        for (int jj = 0; jj < 10; jj++) {
            s0[jj] = unpk_sum(a0[jj]);
            s1[jj] = unpk_sum(a1[jj]);
            s0[jj] += __shfl_xor_sync(0xffffffffu, s0[jj], 2);
            s1[jj] += __shfl_xor_sync(0xffffffffu, s1[jj], 2);
        }
        if (ph == 0 && rp_raw < 25) {
            float* p0 = &s.proj[g][r0][jh * 12];
            float* p1 = &s.proj[g][r1][jh * 12];
#pragma unroll
            for (int jj = 0; jj < 10; jj++) { p0[jj] = s0[jj]; p1[jj] = s1[jj]; }
        }
        __syncthreads();   // emb reads + proj writes done before next stage
    }

    // ---------------- Phase 2: normalized adjacency M (emb buffer dead) ----------------
    {
        float* mflat = &s.big.M[0][0][0];
        for (int i = t; i < 2 * NN * 53; i += TPB) mflat[i] = 0.0f;
    }
    for (int i = t; i < 2 * NN; i += TPB) {
        int g = i / NN, n = i - (i / NN) * NN;
        s.dinv[g][n] = rsqrtf(s.dinv[g][n]);
    }
    for (int i = t; i < NN * NN; i += TPB) s.wa.attn[i / NN][i % NN] = attn[i]; // Wt dead
    __syncthreads();
    for (int i = t; i < 2 * E; i += TPB) {
        int g = i / E, e = i - g * E;
        unsigned v = s.edge[g][e];
        int sr = v & 255, ds = v >> 8;
        atomicAdd(&s.big.M[g][ds][sr], s.dinv[g][sr] * s.dinv[g][ds]);
    }
    __syncthreads();
    if (t < 100) {
        int g = t / NN, n = t - (t / NN) * NN;
        float dn = s.dinv[g][n];
        s.big.M[g][n][n] += dn * dn;
    }
    __syncthreads();

    // ---------------- Phase 3: GCN-GEMV + cross-GEMV + cosine + MLPs ----------------
    const int g3 = (t < 100) ? (t / NN) : 0;
    const int n3 = (t < 100) ? (t - g3 * NN) : 0;
    float h2a[20];
    if (t < 100) {
        float sv[10], cv[10];
#pragma unroll
        for (int j = 0; j < 10; j++) { sv[j] = 0.0f; cv[j] = 0.0f; }
        const float* Mrow = &s.big.M[g3][n3][0];
        const float* Arow = &s.wa.attn[n3][0];
        const float* pabase = &s.proj[g3][0][0];
        const float* pbbase = &s.proj[1 - g3][0][12];
#pragma unroll 2
        for (int m = 0; m < NN; m++) {
            float Mv = Mrow[m];
            float Av = Arow[m];
            const float* pa = pabase + m * 24;
            const float* pb = pbbase + m * 24;
            float4 A0 = *reinterpret_cast<const float4*>(pa);
            float4 A1 = *reinterpret_cast<const float4*>(pa + 4);
            float2 A2 = *reinterpret_cast<const float2*>(pa + 8);
            float4 B0 = *reinterpret_cast<const float4*>(pb);
            float4 B1 = *reinterpret_cast<const float4*>(pb + 4);
            float2 B2 = *reinterpret_cast<const float2*>(pb + 8);
            sv[0] += Mv * A0.x; sv[1] += Mv * A0.y; sv[2] += Mv * A0.z; sv[3] += Mv * A0.w;
            sv[4] += Mv * A1.x; sv[5] += Mv * A1.y; sv[6] += Mv * A1.z; sv[7] += Mv * A1.w;
            sv[8] += Mv * A2.x; sv[9] += Mv * A2.y;
            cv[0] += Av * B0.x; cv[1] += Av * B0.y; cv[2] += Av * B0.z; cv[3] += Av * B0.w;
            cv[4] += Av * B1.x; cv[5] += Av * B1.y; cv[6] += Av * B1.z; cv[7] += Av * B1.w;
            cv[8] += Av * B2.x; cv[9] += Av * B2.y;
        }
        float dot = 0.0f, na = 0.0f, nc = 0.0f;
#pragma unroll
        for (int j = 0; j < 10; j++) {
            sv[j] += s.convb[j];
            float aw = s.assign[n3][j];
            float av = aw * sv[j], cw2 = aw * cv[j];
            dot += av * cw2; na += av * av; nc += cw2 * cw2;
        }
        na = fmaxf(sqrtf(na), EPSV);
        nc = fmaxf(sqrtf(nc), EPSV);
        float dist = dot / (na * nc);

        // MLP layer 1 (h1 stays in registers)
        float h1r[20];
#pragma unroll
        for (int j = 0; j < 20; j++) {
            float a = s.mpb1[j] + dist * s.mpw1[0][j];
#pragma unroll
            for (int k = 0; k < 10; k++) a += sv[k] * s.mpw1[k + 1][j];
            h1r[j] = fmaxf(a, 0.0f);
        }
        // MLP layer 2
#pragma unroll
        for (int j = 0; j < 20; j++) h2a[j] = s.mpb2[j];
#pragma unroll 4
        for (int k = 0; k < 20; k++) {
            float hk = h1r[k];
#pragma unroll
            for (int j = 0; j < 20; j++) h2a[j] += hk * s.mpw2[k][j];
        }
    }
    __syncthreads();   // M/attn/proj reads done before h2 overwrites union
    if (t < 100) {
#pragma unroll
        for (int j = 0; j < 20; j++) s.big.h2[g3][n3][j] = h2a[j];
    }
    __syncthreads();

    // ---------------- Phase 4: node-max, features, FFN, sigmoid ----------------
    if (t < 40) {
        int g = t / 20, j = t - g * 20;
        float m = -3.4e38f;
        for (int n = 0; n < NN; n++) m = fmaxf(m, s.big.h2[g][n][j]);
        s.gmax[g][j] = m;
    }
    __syncthreads();
    if (t < 80) {
        int q = t / 20, i = t - q * 20;
        float gu = s.gmax[0][i], gr = s.gmax[1][i];
        float v = (q == 0) ? gu : (q == 1) ? gr : (q == 2) ? gu * gr : fabsf(gu - gr);
        s.feat[t] = v;
    }
    __syncthreads();
    if (t < 40) {
        float a = fb1[t];
        for (int i = 0; i < 80; i++) a += s.feat[i] * fw1[i * 40 + t];
        s.z[t] = fmaxf(a, 0.0f);
    }
    __syncthreads();
    if (t == 0) {
        float lg = fb2[0];
        for (int i = 0; i < 40; i++) lg += s.z[i] * fw2[i];
        out[b] = 1.0f / (1.0f + expf(-lg));
    }
}

extern "C" void kernel_launch(void* const* d_in, const int* in_sizes, int n_in,
                              void* d_out, int out_size) {
    const int* utok   = (const int*)d_in[0];
    const int* rtok   = (const int*)d_in[1];
    const int* uadj   = (const int*)d_in[2];
    const int* radj   = (const int*)d_in[3];
    const float* emb  = (const float*)d_in[4];
    const float* cw   = (const float*)d_in[5];
    const float* cb   = (const float*)d_in[6];
    const float* xw   = (const float*)d_in[7];
    const float* attn = (const float*)d_in[8];
    const float* asw  = (const float*)d_in[9];
    const float* mw1  = (const float*)d_in[10];
    const float* mb1  = (const float*)d_in[11];
    const float* mw2  = (const float*)d_in[12];
    const float* mb2  = (const float*)d_in[13];
    const float* fw1  = (const float*)d_in[14];
    const float* fb1  = (const float*)d_in[15];
    const float* fw2  = (const float*)d_in[16];
    const float* fb2  = (const float*)d_in[17];
    float* out = (float*)d_out;

    int B = in_sizes[0] / NN;
    int E = in_sizes[2] / (2 * B);

    cudaFuncSetAttribute(gmn_kernel, cudaFuncAttributeMaxDynamicSharedMemorySize,
                         (int)sizeof(Smem));
    gmn_kernel<<<B, TPB, sizeof(Smem)>>>(utok, rtok, uadj, radj, emb,
                                         cw, cb, xw, attn, asw,
                                         mw1, mb1, mw2, mb2,
                                         fw1, fb1, fw2, fb2,
                                         out, E);
}

// round 3
// speedup vs baseline: 1.9386x; 1.5509x over previous
#include <cuda_runtime.h>

#define NN 50
#define TPB 128
#define EPSV 1e-8f
#define EMAXE 512
#define VOCAB 21128

// Precomputed projected embedding table: row v = [emb[v]@conv_w (10) | emb[v]@cross_w (10)]
__device__ float g_ptab[VOCAB * 20];

__device__ __forceinline__ unsigned long long pk2(float a, float b) {
    union { float2 f; unsigned long long u; } c;
    c.f = make_float2(a, b);
    return c.u;
}
__device__ __forceinline__ float unpk_sum(unsigned long long u) {
    union { float2 f; unsigned long long u; } c;
    c.u = u;
    return c.f.x + c.f.y;
}
#define FMA2(d, a, b) asm("fma.rn.f32x2 %0, %1, %2, %0;" : "+l"(d) : "l"(a), "l"(b))

// ---------------- Precompute kernel: g_ptab = emb_table @ [conv_w | cross_w] ----------------
__global__ void __launch_bounds__(128) ptab_kernel(
    const float* __restrict__ emb,
    const float* __restrict__ conv_w,
    const float* __restrict__ cross_w)
{
    __shared__ float wt[20][132];
    const int t = threadIdx.x;
    for (int i = t; i < 20 * 128; i += 128) {
        int j = i >> 7, d = i & 127;
        wt[j][d] = (j < 10) ? conv_w[d * 10 + j] : cross_w[d * 10 + (j - 10)];
    }
    __syncthreads();
    int v = blockIdx.x * 128 + t;
    if (v >= VOCAB) return;

    unsigned long long acc[20];
#pragma unroll
    for (int j = 0; j < 20; j++) acc[j] = 0ull;
    const float4* ep = reinterpret_cast<const float4*>(emb + (size_t)v * 128);
#pragma unroll 4
    for (int c4 = 0; c4 < 32; c4++) {
        float4 e = ep[c4];
        unsigned long long e01 = pk2(e.x, e.y), e23 = pk2(e.z, e.w);
#pragma unroll
        for (int j = 0; j < 20; j++) {
            float4 w = *reinterpret_cast<const float4*>(&wt[j][c4 * 4]);
            unsigned long long w01 = pk2(w.x, w.y), w23 = pk2(w.z, w.w);
            FMA2(acc[j], e01, w01);
            FMA2(acc[j], e23, w23);
        }
    }
    float o[20];
#pragma unroll
    for (int j = 0; j < 20; j++) o[j] = unpk_sum(acc[j]);
    float4* op = reinterpret_cast<float4*>(g_ptab + (size_t)v * 20);
#pragma unroll
    for (int k = 0; k < 5; k++)
        op[k] = make_float4(o[k * 4], o[k * 4 + 1], o[k * 4 + 2], o[k * 4 + 3]);
}

// ---------------- Main per-item kernel ----------------
struct Smem {
    union {
        float M[2][NN][53];            // 5300 floats
        float h2[2][NN][21];           // 2100
    } big;
    float attn[NN][51];                // 2550
    float _pad0[2];
    float buf[2][NN][24];              // row: [conv_g 0..9 | cross_other 10..19 | pad]
    float assign[NN][10];
    float mpw1p[11][24];               // rows padded to 24, floats 0..19 valid
    float mpw2p[20][24];
    float mpb1[20], mpb2[20], convb[12];
    float dinv[2][NN];
    float gmax[2][20];
    float pmax[3][2][20];
    float feat[80];
    float zz[2][40];
    int   tok[2][NN];
    unsigned short edge[2][EMAXE];
};

__global__ void __launch_bounds__(TPB, 4) gmn_kernel(
    const int* __restrict__ utok, const int* __restrict__ rtok,
    const int* __restrict__ uadj, const int* __restrict__ radj,
    const float* __restrict__ attn,
    const float* __restrict__ assignw, const float* __restrict__ conv_b,
    const float* __restrict__ mpw1, const float* __restrict__ mpb1,
    const float* __restrict__ mpw2, const float* __restrict__ mpb2,
    const float* __restrict__ fw1, const float* __restrict__ fb1,
    const float* __restrict__ fw2, const float* __restrict__ fb2,
    float* __restrict__ out, int E)
{
    extern __shared__ char smraw[];
    Smem& s = *reinterpret_cast<Smem*>(smraw);
    const int t = threadIdx.x;
    const int b = blockIdx.x;

    // ---------------- Phase 0: cooperative loads ----------------
    for (int i = t; i < 2 * NN; i += TPB) {
        int g = i / NN, n = i - (i / NN) * NN;
        s.tok[g][n] = (g == 0 ? utok : rtok)[b * NN + n];
        s.dinv[g][n] = 1.0f;                    // self-loop degree seed
    }
    for (int i = t; i < 2 * E; i += TPB) {
        int g = i / E, e = i - g * E;
        const int* adj = (g == 0 ? uadj : radj) + (size_t)b * 2 * E;
        int sr = adj[e], ds = adj[E + e];
        s.edge[g][e] = (unsigned short)(sr | (ds << 8));
    }
    for (int i = t; i < NN * NN; i += TPB) s.attn[i / NN][i % NN] = attn[i];
    for (int i = t; i < NN * 10; i += TPB) s.assign[i / 10][i % 10] = assignw[i];
    for (int i = t; i < 11 * 20; i += TPB) s.mpw1p[i / 20][i % 20] = mpw1[i];
    for (int i = t; i < 20 * 20; i += TPB) s.mpw2p[i / 20][i % 20] = mpw2[i];
    if (t < 20) { s.mpb1[t] = mpb1[t]; s.mpb2[t] = mpb2[t]; }
    if (t < 10) s.convb[t] = conv_b[t];
    __syncthreads();

    // ---------------- Phase 0b: degree atomics + proj gather + M zero ----------------
    for (int i = t; i < 2 * E; i += TPB) {
        int g = i / E, e = i - g * E;
        atomicAdd(&s.dinv[g][(s.edge[g][e] >> 8)], 1.0f);
    }
    for (int i = t; i < 2 * NN * 6; i += TPB) {
        int g = i / (NN * 6);
        int rem = i - g * (NN * 6);
        int r = rem / 6, c = rem - r * 6;
        float* dst = &s.buf[g][r][0];
        if (c < 3) {
            const float* tb = g_ptab + (size_t)s.tok[g][r] * 20;
            if (c == 0)      *reinterpret_cast<float4*>(dst)     = *reinterpret_cast<const float4*>(tb);
            else if (c == 1) *reinterpret_cast<float4*>(dst + 4) = *reinterpret_cast<const float4*>(tb + 4);
            else             *reinterpret_cast<float2*>(dst + 8) = *reinterpret_cast<const float2*>(tb + 8);
        } else {
            const float* tb = g_ptab + (size_t)s.tok[1 - g][r] * 20;
            if (c == 3)      *reinterpret_cast<float2*>(dst + 10) = *reinterpret_cast<const float2*>(tb + 10);
            else if (c == 4) *reinterpret_cast<float4*>(dst + 12) = *reinterpret_cast<const float4*>(tb + 12);
            else             *reinterpret_cast<float4*>(dst + 16) = *reinterpret_cast<const float4*>(tb + 16);
        }
    }
    {
        float4* mflat = reinterpret_cast<float4*>(&s.big.M[0][0][0]);
        for (int i = t; i < 2 * NN * 53 / 4; i += TPB) mflat[i] = make_float4(0.f, 0.f, 0.f, 0.f);
    }
    __syncthreads();

    // ---------------- Phase 1: normalize degrees ----------------
    if (t < 2 * NN) {
        int g = t / NN, n = t - g * NN;
        s.dinv[g][n] = rsqrtf(s.dinv[g][n]);
    }
    __syncthreads();

    // ---------------- Phase 2: adjacency atomics ----------------
    for (int i = t; i < 2 * E; i += TPB) {
        int g = i / E, e = i - g * E;
        unsigned v = s.edge[g][e];
        int sr = v & 255, ds = v >> 8;
        atomicAdd(&s.big.M[g][ds][sr], s.dinv[g][sr] * s.dinv[g][ds]);
    }
    __syncthreads();
    if (t < 2 * NN) {
        int g = t / NN, n = t - g * NN;
        float dn = s.dinv[g][n];
        s.big.M[g][n][n] += dn * dn;
    }
    __syncthreads();

    // ---------------- Phase 3: GCN + cross matvecs, cosine, MLPs ----------------
    float h2a[20];
    const int g3 = (t < 100) ? (t / NN) : 0;
    const int n3 = (t < 100) ? (t - g3 * NN) : 0;
    if (t < 100) {
        float sv[10], cv[10];
#pragma unroll
        for (int j = 0; j < 10; j++) { sv[j] = 0.0f; cv[j] = 0.0f; }
        const float* Mrow = &s.big.M[g3][n3][0];
        const float* Arow = &s.attn[n3][0];
        const float* prow = &s.buf[g3][0][0];
#pragma unroll 5
        for (int m = 0; m < NN; m++) {
            float Mv = Mrow[m], Av = Arow[m];
            const float* pr = prow + m * 24;
            float4 P0 = *reinterpret_cast<const float4*>(pr);
            float4 P1 = *reinterpret_cast<const float4*>(pr + 4);
            float4 P2 = *reinterpret_cast<const float4*>(pr + 8);
            float4 P3 = *reinterpret_cast<const float4*>(pr + 12);
            float4 P4 = *reinterpret_cast<const float4*>(pr + 16);
            sv[0] += Mv * P0.x; sv[1] += Mv * P0.y; sv[2] += Mv * P0.z; sv[3] += Mv * P0.w;
            sv[4] += Mv * P1.x; sv[5] += Mv * P1.y; sv[6] += Mv * P1.z; sv[7] += Mv * P1.w;
            sv[8] += Mv * P2.x; sv[9] += Mv * P2.y;
            cv[0] += Av * P2.z; cv[1] += Av * P2.w;
            cv[2] += Av * P3.x; cv[3] += Av * P3.y; cv[4] += Av * P3.z; cv[5] += Av * P3.w;
            cv[6] += Av * P4.x; cv[7] += Av * P4.y; cv[8] += Av * P4.z; cv[9] += Av * P4.w;
        }
        float dot = 0.0f, na = 0.0f, nc = 0.0f;
#pragma unroll
        for (int j = 0; j < 10; j++) {
            sv[j] += s.convb[j];
            float aw = s.assign[n3][j];
            float av = aw * sv[j], cw2 = aw * cv[j];
            dot += av * cw2; na += av * av; nc += cw2 * cw2;
        }
        na = fmaxf(sqrtf(na), EPSV);
        nc = fmaxf(sqrtf(nc), EPSV);
        float dist = dot / (na * nc);

        // MLP layer 1 (vectorized weight reads)
        float a[20];
#pragma unroll
        for (int jj = 0; jj < 5; jj++) {
            float4 bb = *reinterpret_cast<const float4*>(&s.mpb1[jj * 4]);
            float4 w0 = *reinterpret_cast<const float4*>(&s.mpw1p[0][jj * 4]);
            a[jj * 4 + 0] = bb.x + dist * w0.x;
            a[jj * 4 + 1] = bb.y + dist * w0.y;
            a[jj * 4 + 2] = bb.z + dist * w0.z;
            a[jj * 4 + 3] = bb.w + dist * w0.w;
        }
#pragma unroll
        for (int k = 0; k < 10; k++) {
            float x = sv[k];
            const float* wr = &s.mpw1p[k + 1][0];
#pragma unroll
            for (int jj = 0; jj < 5; jj++) {
                float4 w = *reinterpret_cast<const float4*>(wr + jj * 4);
                a[jj * 4 + 0] += x * w.x; a[jj * 4 + 1] += x * w.y;
                a[jj * 4 + 2] += x * w.z; a[jj * 4 + 3] += x * w.w;
            }
        }
        float h1f[20];
#pragma unroll
        for (int j = 0; j < 20; j++) h1f[j] = fmaxf(a[j], 0.0f);

        // MLP layer 2
#pragma unroll
        for (int jj = 0; jj < 5; jj++) {
            float4 bb = *reinterpret_cast<const float4*>(&s.mpb2[jj * 4]);
            h2a[jj * 4 + 0] = bb.x; h2a[jj * 4 + 1] = bb.y;
            h2a[jj * 4 + 2] = bb.z; h2a[jj * 4 + 3] = bb.w;
        }
#pragma unroll
        for (int k = 0; k < 20; k++) {
            float x = h1f[k];
            const float* wr = &s.mpw2p[k][0];
#pragma unroll
            for (int jj = 0; jj < 5; jj++) {
                float4 w = *reinterpret_cast<const float4*>(wr + jj * 4);
                h2a[jj * 4 + 0] += x * w.x; h2a[jj * 4 + 1] += x * w.y;
                h2a[jj * 4 + 2] += x * w.z; h2a[jj * 4 + 3] += x * w.w;
            }
        }
    }
    __syncthreads();   // all M/attn/buf reads done before h2 overwrites union
    if (t < 100) {
#pragma unroll
        for (int j = 0; j < 20; j++) s.big.h2[g3][n3][j] = h2a[j];
    }
    __syncthreads();

    // ---------------- Phase 4: node-max (3-way split), features, FFN ----------------
    if (t < 120) {
        int q = t / 40, r = t - q * 40;
        int g = r / 20, j = r - g * 20;
        int n0 = q * 17, n1 = (q == 2) ? NN : (q + 1) * 17;
        float m = -3.4e38f;
        for (int n = n0; n < n1; n++) m = fmaxf(m, s.big.h2[g][n][j]);
        s.pmax[q][g][j] = m;
    }
    __syncthreads();
    if (t < 40) {
        int g = t / 20, j = t - g * 20;
        s.gmax[g][j] = fmaxf(s.pmax[0][g][j], fmaxf(s.pmax[1][g][j], s.pmax[2][g][j]));
    }
    __syncthreads();
    if (t < 80) {
        int q = t / 20, i = t - q * 20;
        float gu = s.gmax[0][i], gr = s.gmax[1][i];
        s.feat[t] = (q == 0) ? gu : (q == 1) ? gr : (q == 2) ? gu * gr : fabsf(gu - gr);
    }
    __syncthreads();
    if (t < 80) {
        int half = t / 40, o = t - half * 40;
        float acc = half ? 0.0f : fb1[o];
        for (int i = half * 40; i < half * 40 + 40; i++)
            acc += s.feat[i] * fw1[i * 40 + o];
        s.zz[half][o] = acc;
    }
    __syncthreads();
    if (t == 0) {
        float lg = fb2[0];
        for (int i = 0; i < 40; i++) {
            float z = fmaxf(s.zz[0][i] + s.zz[1][i], 0.0f);
            lg += z * fw2[i];
        }
        out[b] = 1.0f / (1.0f + expf(-lg));
    }
}

extern "C" void kernel_launch(void* const* d_in, const int* in_sizes, int n_in,
                              void* d_out, int out_size) {
    const int* utok   = (const int*)d_in[0];
    const int* rtok   = (const int*)d_in[1];
    const int* uadj   = (const int*)d_in[2];
    const int* radj   = (const int*)d_in[3];
    const float* emb  = (const float*)d_in[4];
    const float* cw   = (const float*)d_in[5];
    const float* cb   = (const float*)d_in[6];
    const float* xw   = (const float*)d_in[7];
    const float* attn = (const float*)d_in[8];
    const float* asw  = (const float*)d_in[9];
    const float* mw1  = (const float*)d_in[10];
    const float* mb1  = (const float*)d_in[11];
    const float* mw2  = (const float*)d_in[12];
    const float* mb2  = (const float*)d_in[13];
    const float* fw1  = (const float*)d_in[14];
    const float* fb1  = (const float*)d_in[15];
    const float* fw2  = (const float*)d_in[16];
    const float* fb2  = (const float*)d_in[17];
    float* out = (float*)d_out;

    int B = in_sizes[0] / NN;
    int E = in_sizes[2] / (2 * B);

    ptab_kernel<<<(VOCAB + 127) / 128, 128>>>(emb, cw, xw);

    cudaFuncSetAttribute(gmn_kernel, cudaFuncAttributeMaxDynamicSharedMemorySize,
                         (int)sizeof(Smem));
    gmn_kernel<<<B, TPB, sizeof(Smem)>>>(utok, rtok, uadj, radj,
                                         attn, asw, cb,
                                         mw1, mb1, mw2, mb2,
                                         fw1, fb1, fw2, fb2,
                                         out, E);
}

// round 4
// speedup vs baseline: 2.2006x; 1.1352x over previous
#include <cuda_runtime.h>

#define NN 50
#define TPB 128
#define EPSV 1e-8f
#define EMAXE 512
#define VOCAB 21128

typedef unsigned long long ull;

// Precomputed projected embedding table: row v = [emb[v]@conv_w (10) | emb[v]@cross_w (10)]
__device__ float g_ptab[VOCAB * 20];

__device__ __forceinline__ ull pk2(float a, float b) {
    union { float2 f; ull u; } c;
    c.f = make_float2(a, b);
    return c.u;
}
__device__ __forceinline__ float2 unpk(ull u) {
    union { float2 f; ull u; } c;
    c.u = u;
    return c.f;
}
__device__ __forceinline__ float unpk_sum(ull u) {
    float2 f = unpk(u);
    return f.x + f.y;
}
#define FMA2(d, a, b) asm("fma.rn.f32x2 %0, %1, %2, %0;" : "+l"(d) : "l"(a), "l"(b))

// ---------------- Precompute: g_ptab = emb_table @ [conv_w | cross_w] ----------------
__global__ void __launch_bounds__(128) ptab_kernel(
    const float* __restrict__ emb,
    const float* __restrict__ conv_w,
    const float* __restrict__ cross_w)
{
    __shared__ float wt[20][132];
    const int t = threadIdx.x;
    for (int i = t; i < 20 * 128; i += 128) {
        int j = i >> 7, d = i & 127;
        wt[j][d] = (j < 10) ? conv_w[d * 10 + j] : cross_w[d * 10 + (j - 10)];
    }
    __syncthreads();
    int v = blockIdx.x * 128 + t;
    if (v >= VOCAB) return;

    ull acc[20];
#pragma unroll
    for (int j = 0; j < 20; j++) acc[j] = 0ull;
    const float4* ep = reinterpret_cast<const float4*>(emb + (size_t)v * 128);
#pragma unroll 4
    for (int c4 = 0; c4 < 32; c4++) {
        float4 e = ep[c4];
        ull e01 = pk2(e.x, e.y), e23 = pk2(e.z, e.w);
#pragma unroll
        for (int j = 0; j < 20; j++) {
            float4 w = *reinterpret_cast<const float4*>(&wt[j][c4 * 4]);
            FMA2(acc[j], e01, pk2(w.x, w.y));
            FMA2(acc[j], e23, pk2(w.z, w.w));
        }
    }
    float o[20];
#pragma unroll
    for (int j = 0; j < 20; j++) o[j] = unpk_sum(acc[j]);
    float4* op = reinterpret_cast<float4*>(g_ptab + (size_t)v * 20);
#pragma unroll
    for (int k = 0; k < 5; k++)
        op[k] = make_float4(o[k * 4], o[k * 4 + 1], o[k * 4 + 2], o[k * 4 + 3]);
}

// ---------------- Main per-item kernel ----------------
struct Smem {
    union {
        float acc[2][10][52];          // transposed GCN accumulators (phase 2/3)
        float h2[2][NN][21];           // 2100 floats (phase 3/4)
    } big;
    float attn[NN][51];                // 2550
    float _padA[2];
    float convp[2][NN][12];            // conv proj of graph g tokens (pads zeroed)
    float crossp[2][NN][12];           // cross proj of graph g tokens (pads zeroed)
    float assign[NN][10];
    float mpw1p[11][20];
    float mpw2p[20][20];
    float mpb1[20], mpb2[20], convb[12];
    float dinv[2][NN];
    float gmax[2][20];
    float pmax[3][2][20];
    float feat[80];
    float zz[2][40];
    int   tok[2][NN];
    unsigned short edge[2][EMAXE];
};

__global__ void __launch_bounds__(TPB, 6) gmn_kernel(
    const int* __restrict__ utok, const int* __restrict__ rtok,
    const int* __restrict__ uadj, const int* __restrict__ radj,
    const float* __restrict__ attn,
    const float* __restrict__ assignw, const float* __restrict__ conv_b,
    const float* __restrict__ mpw1, const float* __restrict__ mpb1,
    const float* __restrict__ mpw2, const float* __restrict__ mpb2,
    const float* __restrict__ fw1, const float* __restrict__ fb1,
    const float* __restrict__ fw2, const float* __restrict__ fb2,
    float* __restrict__ out, int E)
{
    extern __shared__ char smraw[];
    Smem& s = *reinterpret_cast<Smem*>(smraw);
    const int t = threadIdx.x;
    const int b = blockIdx.x;

    // ---------------- Phase 0: cooperative loads + zero acc ----------------
    for (int i = t; i < 2 * NN; i += TPB) {
        int g = i / NN, n = i - (i / NN) * NN;
        s.tok[g][n] = (g == 0 ? utok : rtok)[b * NN + n];
        s.dinv[g][n] = 1.0f;                    // self-loop degree seed
    }
    for (int i = t; i < 2 * E; i += TPB) {
        int g = i / E, e = i - g * E;
        const int* adj = (g == 0 ? uadj : radj) + (size_t)b * 2 * E;
        int sr = adj[e], ds = adj[E + e];
        s.edge[g][e] = (unsigned short)(sr | (ds << 8));
    }
    for (int i = t; i < NN * NN; i += TPB) s.attn[i / NN][i % NN] = attn[i];
    for (int i = t; i < NN * 10; i += TPB) s.assign[i / 10][i % 10] = assignw[i];
    for (int i = t; i < 11 * 20; i += TPB) s.mpw1p[i / 20][i % 20] = mpw1[i];
    for (int i = t; i < 20 * 20; i += TPB) s.mpw2p[i / 20][i % 20] = mpw2[i];
    if (t < 20) { s.mpb1[t] = mpb1[t]; s.mpb2[t] = mpb2[t]; }
    if (t < 12) s.convb[t] = (t < 10) ? conv_b[t] : 0.0f;
    {
        float4* af = reinterpret_cast<float4*>(&s.big.acc[0][0][0]);
        for (int i = t; i < 2 * 10 * 52 / 4; i += TPB) af[i] = make_float4(0.f, 0.f, 0.f, 0.f);
    }
    __syncthreads();

    // ---------------- Phase 0b: degree atomics + projected-table gather ----------------
    for (int i = t; i < 2 * E; i += TPB) {
        int g = i / E, e = i - g * E;
        atomicAdd(&s.dinv[g][(s.edge[g][e] >> 8)], 1.0f);
    }
    if (t < 100) {
        int g = t / NN, r = t - (t / NN) * NN;
        const float4* tb = reinterpret_cast<const float4*>(g_ptab + (size_t)s.tok[g][r] * 20);
        float4 v0 = tb[0], v1 = tb[1], v2 = tb[2], v3 = tb[3], v4 = tb[4];
        float4* cp = reinterpret_cast<float4*>(&s.convp[g][r][0]);
        cp[0] = v0;
        cp[1] = v1;
        cp[2] = make_float4(v2.x, v2.y, 0.f, 0.f);
        float4* xp = reinterpret_cast<float4*>(&s.crossp[g][r][0]);
        xp[0] = make_float4(v2.z, v2.w, v3.x, v3.y);
        xp[1] = make_float4(v3.z, v3.w, v4.x, v4.y);
        xp[2] = make_float4(v4.z, v4.w, 0.f, 0.f);
    }
    __syncthreads();

    // ---------------- Phase 1: normalize degrees ----------------
    if (t < 2 * NN) {
        int g = t / NN, n = t - g * NN;
        s.dinv[g][n] = rsqrtf(s.dinv[g][n]);
    }
    __syncthreads();

    // ---------------- Phase 2: edge-scatter GCN aggregation ----------------
    // task = (g, e, half): acc[g][half*5+j][ds] += norm * convp[g][sr][half*5+j]
    for (int i = t; i < 4 * E; i += TPB) {
        int g = i / (2 * E);
        int rem = i - g * 2 * E;
        int e = rem >> 1, half = (rem & 1) * 5;
        unsigned v = s.edge[g][e];
        int sr = v & 255, ds = v >> 8;
        float norm = s.dinv[g][sr] * s.dinv[g][ds];
        const float* cp = &s.convp[g][sr][half];
#pragma unroll
        for (int j = 0; j < 5; j++)
            atomicAdd(&s.big.acc[g][half + j][ds], norm * cp[j]);
    }
    __syncthreads();

    // ---------------- Phase 3: self-loop + cross matvec + cosine + MLPs ----------------
    float h2f[20];
    const int g3 = (t < 100) ? (t / NN) : 0;
    const int n3 = (t < 100) ? (t - g3 * NN) : 0;
    if (t < 100) {
        float dn = s.dinv[g3][n3];
        float d2 = dn * dn;
        float sv[10];
#pragma unroll
        for (int j = 0; j < 10; j++)
            sv[j] = s.big.acc[g3][j][n3] + d2 * s.convp[g3][n3][j] + s.convb[j];

        // cross matvec: cv = attn[n3,:] @ crossp[other]
        ull cacc[6];
#pragma unroll
        for (int p = 0; p < 6; p++) cacc[p] = 0ull;
        const float* Arow = &s.attn[n3][0];
        const ull* cbase = reinterpret_cast<const ull*>(&s.crossp[1 - g3][0][0]);
#pragma unroll 5
        for (int m = 0; m < NN; m++) {
            float Av = Arow[m];
            ull av2 = pk2(Av, Av);
            const ull* cr = cbase + m * 6;
            ulonglong2 L0 = *reinterpret_cast<const ulonglong2*>(cr);
            ulonglong2 L1 = *reinterpret_cast<const ulonglong2*>(cr + 2);
            ulonglong2 L2 = *reinterpret_cast<const ulonglong2*>(cr + 4);
            FMA2(cacc[0], av2, L0.x); FMA2(cacc[1], av2, L0.y);
            FMA2(cacc[2], av2, L1.x); FMA2(cacc[3], av2, L1.y);
            FMA2(cacc[4], av2, L2.x); FMA2(cacc[5], av2, L2.y);
        }
        float cv[10];
#pragma unroll
        for (int p = 0; p < 5; p++) {
            float2 f = unpk(cacc[p]);
            cv[p * 2] = f.x; cv[p * 2 + 1] = f.y;
        }

        // cosine with assign weighting
        float dot = 0.0f, na = 0.0f, nc = 0.0f;
#pragma unroll
        for (int j = 0; j < 10; j++) {
            float aw = s.assign[n3][j];
            float av = aw * sv[j], cw2 = aw * cv[j];
            dot += av * cw2; na += av * av; nc += cw2 * cw2;
        }
        na = fmaxf(sqrtf(na), EPSV);
        nc = fmaxf(sqrtf(nc), EPSV);
        float dist = dot / (na * nc);

        // MLP layer 1 (packed f32x2)
        ull aa[10];
        {
            const ull* bb = reinterpret_cast<const ull*>(&s.mpb1[0]);
            const ull* w0 = reinterpret_cast<const ull*>(&s.mpw1p[0][0]);
            ull dd = pk2(dist, dist);
#pragma unroll
            for (int p = 0; p < 10; p++) { aa[p] = bb[p]; FMA2(aa[p], dd, w0[p]); }
#pragma unroll
            for (int k = 0; k < 10; k++) {
                ull xx = pk2(sv[k], sv[k]);
                const ulonglong2* wr = reinterpret_cast<const ulonglong2*>(&s.mpw1p[k + 1][0]);
                ulonglong2 W0 = wr[0], W1 = wr[1], W2 = wr[2], W3 = wr[3], W4 = wr[4];
                FMA2(aa[0], xx, W0.x); FMA2(aa[1], xx, W0.y);
                FMA2(aa[2], xx, W1.x); FMA2(aa[3], xx, W1.y);
                FMA2(aa[4], xx, W2.x); FMA2(aa[5], xx, W2.y);
                FMA2(aa[6], xx, W3.x); FMA2(aa[7], xx, W3.y);
                FMA2(aa[8], xx, W4.x); FMA2(aa[9], xx, W4.y);
            }
        }
        float h1f[20];
#pragma unroll
        for (int p = 0; p < 10; p++) {
            float2 f = unpk(aa[p]);
            h1f[p * 2] = fmaxf(f.x, 0.0f);
            h1f[p * 2 + 1] = fmaxf(f.y, 0.0f);
        }

        // MLP layer 2 (packed f32x2)
        ull hh[10];
        {
            const ull* bb = reinterpret_cast<const ull*>(&s.mpb2[0]);
#pragma unroll
            for (int p = 0; p < 10; p++) hh[p] = bb[p];
#pragma unroll
            for (int k = 0; k < 20; k++) {
                ull xx = pk2(h1f[k], h1f[k]);
                const ulonglong2* wr = reinterpret_cast<const ulonglong2*>(&s.mpw2p[k][0]);
                ulonglong2 W0 = wr[0], W1 = wr[1], W2 = wr[2], W3 = wr[3], W4 = wr[4];
                FMA2(hh[0], xx, W0.x); FMA2(hh[1], xx, W0.y);
                FMA2(hh[2], xx, W1.x); FMA2(hh[3], xx, W1.y);
                FMA2(hh[4], xx, W2.x); FMA2(hh[5], xx, W2.y);
                FMA2(hh[6], xx, W3.x); FMA2(hh[7], xx, W3.y);
                FMA2(hh[8], xx, W4.x); FMA2(hh[9], xx, W4.y);
            }
        }
#pragma unroll
        for (int p = 0; p < 10; p++) {
            float2 f = unpk(hh[p]);
            h2f[p * 2] = f.x; h2f[p * 2 + 1] = f.y;
        }
    }
    __syncthreads();   // acc/attn/crossp reads done before h2 overwrites union
    if (t < 100) {
#pragma unroll
        for (int j = 0; j < 20; j++) s.big.h2[g3][n3][j] = h2f[j];
    }
    __syncthreads();

    // ---------------- Phase 4: node-max (3-way), features, FFN, sigmoid ----------------
    if (t < 120) {
        int q = t / 40, r = t - q * 40;
        int g = r / 20, j = r - g * 20;
        int n0 = q * 17, n1 = (q == 2) ? NN : (q + 1) * 17;
        float m = -3.4e38f;
        for (int n = n0; n < n1; n++) m = fmaxf(m, s.big.h2[g][n][j]);
        s.pmax[q][g][j] = m;
    }
    __syncthreads();
    if (t < 40) {
        int g = t / 20, j = t - g * 20;
        s.gmax[g][j] = fmaxf(s.pmax[0][g][j], fmaxf(s.pmax[1][g][j], s.pmax[2][g][j]));
    }
    __syncthreads();
    if (t < 80) {
        int q = t / 20, i = t - q * 20;
        float gu = s.gmax[0][i], gr = s.gmax[1][i];
        s.feat[t] = (q == 0) ? gu : (q == 1) ? gr : (q == 2) ? gu * gr : fabsf(gu - gr);
    }
    __syncthreads();
    if (t < 80) {
        int half = t / 40, o = t - half * 40;
        float acc2 = half ? 0.0f : fb1[o];
        for (int i = half * 40; i < half * 40 + 40; i++)
            acc2 += s.feat[i] * fw1[i * 40 + o];
        s.zz[half][o] = acc2;
    }
    __syncthreads();
    if (t == 0) {
        float lg = fb2[0];
        for (int i = 0; i < 40; i++) {
            float z = fmaxf(s.zz[0][i] + s.zz[1][i], 0.0f);
            lg += z * fw2[i];
        }
        out[b] = 1.0f / (1.0f + expf(-lg));
    }
}

extern "C" void kernel_launch(void* const* d_in, const int* in_sizes, int n_in,
                              void* d_out, int out_size) {
    const int* utok   = (const int*)d_in[0];
    const int* rtok   = (const int*)d_in[1];
    const int* uadj   = (const int*)d_in[2];
    const int* radj   = (const int*)d_in[3];
    const float* emb  = (const float*)d_in[4];
    const float* cw   = (const float*)d_in[5];
    const float* cb   = (const float*)d_in[6];
    const float* xw   = (const float*)d_in[7];
    const float* attn = (const float*)d_in[8];
    const float* asw  = (const float*)d_in[9];
    const float* mw1  = (const float*)d_in[10];
    const float* mb1  = (const float*)d_in[11];
    const float* mw2  = (const float*)d_in[12];
    const float* mb2  = (const float*)d_in[13];
    const float* fw1  = (const float*)d_in[14];
    const float* fb1  = (const float*)d_in[15];
    const float* fw2  = (const float*)d_in[16];
    const float* fb2  = (const float*)d_in[17];
    float* out = (float*)d_out;

    int B = in_sizes[0] / NN;
    int E = in_sizes[2] / (2 * B);

    ptab_kernel<<<(VOCAB + 127) / 128, 128>>>(emb, cw, xw);

    cudaFuncSetAttribute(gmn_kernel, cudaFuncAttributeMaxDynamicSharedMemorySize,
                         (int)sizeof(Smem));
    gmn_kernel<<<B, TPB, sizeof(Smem)>>>(utok, rtok, uadj, radj,
                                         attn, asw, cb,
                                         mw1, mb1, mw2, mb2,
                                         fw1, fb1, fw2, fb2,
                                         out, E);
}

// round 5
// speedup vs baseline: 2.9793x; 1.3538x over previous
#include <cuda_runtime.h>

#define NN 50
#define TPB 128
#define EPSV 1e-8f
#define EMAXE 512
#define VOCAB 21128

typedef unsigned long long ull;

// Precomputed projected embedding table: row v = [emb[v]@conv_w (10) | emb[v]@cross_w (10)]
__device__ float g_ptab[VOCAB * 20];

__device__ __forceinline__ ull pk2(float a, float b) {
    union { float2 f; ull u; } c;
    c.f = make_float2(a, b);
    return c.u;
}
__device__ __forceinline__ float2 unpk(ull u) {
    union { float2 f; ull u; } c;
    c.u = u;
    return c.f;
}
__device__ __forceinline__ float unpk_sum(ull u) {
    float2 f = unpk(u);
    return f.x + f.y;
}
#define FMA2(d, a, b) asm("fma.rn.f32x2 %0, %1, %2, %0;" : "+l"(d) : "l"(a), "l"(b))

// ---------------- Precompute: g_ptab = emb_table @ [conv_w | cross_w] ----------------
__global__ void __launch_bounds__(128) ptab_kernel(
    const float* __restrict__ emb,
    const float* __restrict__ conv_w,
    const float* __restrict__ cross_w)
{
    __shared__ float wt[20][132];
    const int t = threadIdx.x;
    for (int i = t; i < 20 * 128; i += 128) {
        int j = i >> 7, d = i & 127;
        wt[j][d] = (j < 10) ? conv_w[d * 10 + j] : cross_w[d * 10 + (j - 10)];
    }
    __syncthreads();
    int v = blockIdx.x * 128 + t;
    if (v >= VOCAB) return;

    ull acc[20];
#pragma unroll
    for (int j = 0; j < 20; j++) acc[j] = 0ull;
    const float4* ep = reinterpret_cast<const float4*>(emb + (size_t)v * 128);
#pragma unroll 4
    for (int c4 = 0; c4 < 32; c4++) {
        float4 e = ep[c4];
        ull e01 = pk2(e.x, e.y), e23 = pk2(e.z, e.w);
#pragma unroll
        for (int j = 0; j < 20; j++) {
            float4 w = *reinterpret_cast<const float4*>(&wt[j][c4 * 4]);
            FMA2(acc[j], e01, pk2(w.x, w.y));
            FMA2(acc[j], e23, pk2(w.z, w.w));
        }
    }
    float o[20];
#pragma unroll
    for (int j = 0; j < 20; j++) o[j] = unpk_sum(acc[j]);
    float4* op = reinterpret_cast<float4*>(g_ptab + (size_t)v * 20);
#pragma unroll
    for (int k = 0; k < 5; k++)
        op[k] = make_float4(o[k * 4], o[k * 4 + 1], o[k * 4 + 2], o[k * 4 + 3]);
}

// ---------------- Main per-item kernel ----------------
struct Smem {
    union {
        float attn[NN][51];            // 2550 floats (phases 0-3)
        float h2[2][NN][21];           // 2100 floats (phase 3 write / phase 4)
    } u;
    float _padA[2];
    float convp[2][NN][12];            // conv proj rows (12-float stride, 16B aligned)
    float crossp[2][NN][12];           // cross proj rows
    float assign[NN][10];
    float mpw1p[11][20];
    float mpw2p[20][20];
    float mpb1[20], mpb2[20], convb[12];
    float dinv[2][NN];
    float gmax[2][20];
    float pmax[3][2][20];
    float feat[80];
    float zz[2][40];
    int   tok[2][NN];
    int   cnt[2][52];                  // per-dst incoming-edge histogram
    int   start[2][52];                // exclusive prefix (start[g][NN] = E)
    int   cur[2][52];                  // scatter cursors
    unsigned short edge[2][EMAXE];     // src | dst<<8
    unsigned short srcsorted[2][EMAXE];// src ids sorted by dst
};

__global__ void __launch_bounds__(TPB, 6) gmn_kernel(
    const int* __restrict__ utok, const int* __restrict__ rtok,
    const int* __restrict__ uadj, const int* __restrict__ radj,
    const float* __restrict__ attn,
    const float* __restrict__ assignw, const float* __restrict__ conv_b,
    const float* __restrict__ mpw1, const float* __restrict__ mpb1,
    const float* __restrict__ mpw2, const float* __restrict__ mpb2,
    const float* __restrict__ fw1, const float* __restrict__ fb1,
    const float* __restrict__ fw2, const float* __restrict__ fb2,
    float* __restrict__ out, int E)
{
    extern __shared__ char smraw[];
    Smem& s = *reinterpret_cast<Smem*>(smraw);
    const int t = threadIdx.x;
    const int b = blockIdx.x;

    // ---------------- Phase 0: cooperative loads + histogram init ----------------
    for (int i = t; i < 2 * NN; i += TPB) {
        int g = i / NN, n = i - (i / NN) * NN;
        s.tok[g][n] = (g == 0 ? utok : rtok)[b * NN + n];
    }
    for (int i = t; i < 2 * E; i += TPB) {
        int g = i / E, e = i - g * E;
        const int* adj = (g == 0 ? uadj : radj) + (size_t)b * 2 * E;
        int sr = adj[e], ds = adj[E + e];
        s.edge[g][e] = (unsigned short)(sr | (ds << 8));
    }
    for (int i = t; i < NN * NN; i += TPB) s.u.attn[i / NN][i % NN] = attn[i];
    for (int i = t; i < NN * 10; i += TPB) s.assign[i / 10][i % 10] = assignw[i];
    for (int i = t; i < 11 * 20; i += TPB) s.mpw1p[i / 20][i % 20] = mpw1[i];
    for (int i = t; i < 20 * 20; i += TPB) s.mpw2p[i / 20][i % 20] = mpw2[i];
    if (t < 20) { s.mpb1[t] = mpb1[t]; s.mpb2[t] = mpb2[t]; }
    if (t < 12) s.convb[t] = (t < 10) ? conv_b[t] : 0.0f;
    if (t < 104) reinterpret_cast<int*>(&s.cnt[0][0])[t] = 0;
    __syncthreads();

    // ---------------- Phase 0b: histogram + projected-table gather ----------------
    for (int i = t; i < 2 * E; i += TPB) {
        int g = i / E, e = i - g * E;
        atomicAdd(&s.cnt[g][(s.edge[g][e] >> 8)], 1);
    }
    if (t < 100) {
        int g = t / NN, r = t - (t / NN) * NN;
        const float4* tb = reinterpret_cast<const float4*>(g_ptab + (size_t)s.tok[g][r] * 20);
        float4 v0 = tb[0], v1 = tb[1], v2 = tb[2], v3 = tb[3], v4 = tb[4];
        float4* cp = reinterpret_cast<float4*>(&s.convp[g][r][0]);
        cp[0] = v0;
        cp[1] = v1;
        cp[2] = make_float4(v2.x, v2.y, 0.f, 0.f);
        float4* xp = reinterpret_cast<float4*>(&s.crossp[g][r][0]);
        xp[0] = make_float4(v2.z, v2.w, v3.x, v3.y);
        xp[1] = make_float4(v3.z, v3.w, v4.x, v4.y);
        xp[2] = make_float4(v4.z, v4.w, 0.f, 0.f);
    }
    __syncthreads();

    // ---------------- Phase 1: prefix scan (2 threads) + dinv from histogram ----------------
    if (t < 2) {
        int acc = 0;
        for (int n = 0; n < NN; n++) {
            s.start[t][n] = acc;
            s.cur[t][n] = acc;
            acc += s.cnt[t][n];
        }
        s.start[t][NN] = acc;
    } else if (t < 102) {
        int idx = t - 2;
        int g = idx / NN, n = idx - g * NN;
        s.dinv[g][n] = rsqrtf((float)(s.cnt[g][n] + 1));
    }
    __syncthreads();

    // ---------------- Phase 2: scatter edges sorted by dst ----------------
    for (int i = t; i < 2 * E; i += TPB) {
        int g = i / E, e = i - g * E;
        unsigned v = s.edge[g][e];
        int sr = v & 255, ds = v >> 8;
        int pos = atomicAdd(&s.cur[g][ds], 1);
        s.srcsorted[g][pos] = (unsigned short)sr;
    }
    __syncthreads();

    // ---------------- Phase 3: gather GCN + cross matvec + cosine + MLPs ----------------
    float h2f[20];
    const int g3 = (t < 100) ? (t / NN) : 0;
    const int n3 = (t < 100) ? (t - g3 * NN) : 0;
    if (t < 100) {
        float dn = s.dinv[g3][n3];
        float d2 = dn * dn;
        // self-loop + bias seed (packed)
        ull sva[5];
        {
            ull d2p = pk2(d2, d2);
            const ull* cb2 = reinterpret_cast<const ull*>(&s.convb[0]);
            const ull* cself = reinterpret_cast<const ull*>(&s.convp[g3][n3][0]);
#pragma unroll
            for (int p = 0; p < 5; p++) { sva[p] = cb2[p]; FMA2(sva[p], d2p, cself[p]); }
        }
        // incoming-edge gather (atomic-free)
        int e0 = s.start[g3][n3], e1 = s.start[g3][n3 + 1];
        for (int i = e0; i < e1; i++) {
            int sr = s.srcsorted[g3][i];
            float norm = dn * s.dinv[g3][sr];
            ull np = pk2(norm, norm);
            const ulonglong2* cr = reinterpret_cast<const ulonglong2*>(&s.convp[g3][sr][0]);
            ulonglong2 C0 = cr[0], C1 = cr[1];
            ull C4 = *reinterpret_cast<const ull*>(&s.convp[g3][sr][8]);
            FMA2(sva[0], np, C0.x); FMA2(sva[1], np, C0.y);
            FMA2(sva[2], np, C1.x); FMA2(sva[3], np, C1.y);
            FMA2(sva[4], np, C4);
        }
        float sv[10];
#pragma unroll
        for (int p = 0; p < 5; p++) {
            float2 f = unpk(sva[p]);
            sv[p * 2] = f.x; sv[p * 2 + 1] = f.y;
        }

        // cross matvec: cv = attn[n3,:] @ crossp[other]
        ull cacc[5];
#pragma unroll
        for (int p = 0; p < 5; p++) cacc[p] = 0ull;
        const float* Arow = &s.u.attn[n3][0];
        const float* cbase = &s.crossp[1 - g3][0][0];
#pragma unroll 5
        for (int m = 0; m < NN; m++) {
            float Av = Arow[m];
            ull av2 = pk2(Av, Av);
            const ulonglong2* cr = reinterpret_cast<const ulonglong2*>(cbase + m * 12);
            ulonglong2 L0 = cr[0], L1 = cr[1];
            ull L4 = *reinterpret_cast<const ull*>(cbase + m * 12 + 8);
            FMA2(cacc[0], av2, L0.x); FMA2(cacc[1], av2, L0.y);
            FMA2(cacc[2], av2, L1.x); FMA2(cacc[3], av2, L1.y);
            FMA2(cacc[4], av2, L4);
        }
        float cv[10];
#pragma unroll
        for (int p = 0; p < 5; p++) {
            float2 f = unpk(cacc[p]);
            cv[p * 2] = f.x; cv[p * 2 + 1] = f.y;
        }

        // cosine with assign weighting
        float dot = 0.0f, na = 0.0f, nc = 0.0f;
#pragma unroll
        for (int j = 0; j < 10; j++) {
            float aw = s.assign[n3][j];
            float av = aw * sv[j], cw2 = aw * cv[j];
            dot += av * cw2; na += av * av; nc += cw2 * cw2;
        }
        na = fmaxf(sqrtf(na), EPSV);
        nc = fmaxf(sqrtf(nc), EPSV);
        float dist = dot / (na * nc);

        // MLP layer 1 (packed)
        ull aa[10];
        {
            const ull* bb = reinterpret_cast<const ull*>(&s.mpb1[0]);
            const ull* w0 = reinterpret_cast<const ull*>(&s.mpw1p[0][0]);
            ull dd = pk2(dist, dist);
#pragma unroll
            for (int p = 0; p < 10; p++) { aa[p] = bb[p]; FMA2(aa[p], dd, w0[p]); }
#pragma unroll
            for (int k = 0; k < 10; k++) {
                ull xx = pk2(sv[k], sv[k]);
                const ulonglong2* wr = reinterpret_cast<const ulonglong2*>(&s.mpw1p[k + 1][0]);
                ulonglong2 W0 = wr[0], W1 = wr[1], W2 = wr[2], W3 = wr[3], W4 = wr[4];
                FMA2(aa[0], xx, W0.x); FMA2(aa[1], xx, W0.y);
                FMA2(aa[2], xx, W1.x); FMA2(aa[3], xx, W1.y);
                FMA2(aa[4], xx, W2.x); FMA2(aa[5], xx, W2.y);
                FMA2(aa[6], xx, W3.x); FMA2(aa[7], xx, W3.y);
                FMA2(aa[8], xx, W4.x); FMA2(aa[9], xx, W4.y);
            }
        }
        float h1f[20];
#pragma unroll
        for (int p = 0; p < 10; p++) {
            float2 f = unpk(aa[p]);
            h1f[p * 2] = fmaxf(f.x, 0.0f);
            h1f[p * 2 + 1] = fmaxf(f.y, 0.0f);
        }

        // MLP layer 2 (packed)
        ull hh[10];
        {
            const ull* bb = reinterpret_cast<const ull*>(&s.mpb2[0]);
#pragma unroll
            for (int p = 0; p < 10; p++) hh[p] = bb[p];
#pragma unroll
            for (int k = 0; k < 20; k++) {
                ull xx = pk2(h1f[k], h1f[k]);
                const ulonglong2* wr = reinterpret_cast<const ulonglong2*>(&s.mpw2p[k][0]);
                ulonglong2 W0 = wr[0], W1 = wr[1], W2 = wr[2], W3 = wr[3], W4 = wr[4];
                FMA2(hh[0], xx, W0.x); FMA2(hh[1], xx, W0.y);
                FMA2(hh[2], xx, W1.x); FMA2(hh[3], xx, W1.y);
                FMA2(hh[4], xx, W2.x); FMA2(hh[5], xx, W2.y);
                FMA2(hh[6], xx, W3.x); FMA2(hh[7], xx, W3.y);
                FMA2(hh[8], xx, W4.x); FMA2(hh[9], xx, W4.y);
            }
        }
#pragma unroll
        for (int p = 0; p < 10; p++) {
            float2 f = unpk(hh[p]);
            h2f[p * 2] = f.x; h2f[p * 2 + 1] = f.y;
        }
    }
    __syncthreads();   // attn reads done before h2 overwrites the union
    if (t < 100) {
#pragma unroll
        for (int j = 0; j < 20; j++) s.u.h2[g3][n3][j] = h2f[j];
    }
    __syncthreads();

    // ---------------- Phase 4: node-max (3-way), features, FFN, sigmoid ----------------
    if (t < 120) {
        int q = t / 40, r = t - q * 40;
        int g = r / 20, j = r - g * 20;
        int n0 = q * 17, n1 = (q == 2) ? NN : (q + 1) * 17;
        float m = -3.4e38f;
        for (int n = n0; n < n1; n++) m = fmaxf(m, s.u.h2[g][n][j]);
        s.pmax[q][g][j] = m;
    }
    __syncthreads();
    if (t < 40) {
        int g = t / 20, j = t - g * 20;
        s.gmax[g][j] = fmaxf(s.pmax[0][g][j], fmaxf(s.pmax[1][g][j], s.pmax[2][g][j]));
    }
    __syncthreads();
    if (t < 80) {
        int q = t / 20, i = t - q * 20;
        float gu = s.gmax[0][i], gr = s.gmax[1][i];
        s.feat[t] = (q == 0) ? gu : (q == 1) ? gr : (q == 2) ? gu * gr : fabsf(gu - gr);
    }
    __syncthreads();
    if (t < 80) {
        int half = t / 40, o = t - half * 40;
        float acc2 = half ? 0.0f : fb1[o];
        for (int i = half * 40; i < half * 40 + 40; i++)
            acc2 += s.feat[i] * fw1[i * 40 + o];
        s.zz[half][o] = acc2;
    }
    __syncthreads();
    if (t == 0) {
        float lg = fb2[0];
        for (int i = 0; i < 40; i++) {
            float z = fmaxf(s.zz[0][i] + s.zz[1][i], 0.0f);
            lg += z * fw2[i];
        }
        out[b] = 1.0f / (1.0f + expf(-lg));
    }
}

extern "C" void kernel_launch(void* const* d_in, const int* in_sizes, int n_in,
                              void* d_out, int out_size) {
    const int* utok   = (const int*)d_in[0];
    const int* rtok   = (const int*)d_in[1];
    const int* uadj   = (const int*)d_in[2];
    const int* radj   = (const int*)d_in[3];
    const float* emb  = (const float*)d_in[4];
    const float* cw   = (const float*)d_in[5];
    const float* cb   = (const float*)d_in[6];
    const float* xw   = (const float*)d_in[7];
    const float* attn = (const float*)d_in[8];
    const float* asw  = (const float*)d_in[9];
    const float* mw1  = (const float*)d_in[10];
    const float* mb1  = (const float*)d_in[11];
    const float* mw2  = (const float*)d_in[12];
    const float* mb2  = (const float*)d_in[13];
    const float* fw1  = (const float*)d_in[14];
    const float* fb1  = (const float*)d_in[15];
    const float* fw2  = (const float*)d_in[16];
    const float* fb2  = (const float*)d_in[17];
    float* out = (float*)d_out;

    int B = in_sizes[0] / NN;
    int E = in_sizes[2] / (2 * B);

    ptab_kernel<<<(VOCAB + 127) / 128, 128>>>(emb, cw, xw);

    cudaFuncSetAttribute(gmn_kernel, cudaFuncAttributeMaxDynamicSharedMemorySize,
                         (int)sizeof(Smem));
    gmn_kernel<<<B, TPB, sizeof(Smem)>>>(utok, rtok, uadj, radj,
                                         attn, asw, cb,
                                         mw1, mb1, mw2, mb2,
                                         fw1, fb1, fw2, fb2,
                                         out, E);
}

// round 6
// speedup vs baseline: 3.1278x; 1.0499x over previous
#include <cuda_runtime.h>

#define NN 50
#define TPB 128
#define EPSV 1e-8f
#define EMAXE 256
#define VOCAB 21128

typedef unsigned long long ull;

// Precomputed projected embedding table: row v = [emb[v]@conv_w (10) | emb[v]@cross_w (10)]
__device__ float g_ptab[VOCAB * 20];

__device__ __forceinline__ ull pk2(float a, float b) {
    union { float2 f; ull u; } c;
    c.f = make_float2(a, b);
    return c.u;
}
__device__ __forceinline__ float2 unpk(ull u) {
    union { float2 f; ull u; } c;
    c.u = u;
    return c.f;
}
__device__ __forceinline__ float unpk_sum(ull u) {
    float2 f = unpk(u);
    return f.x + f.y;
}
#define FMA2(d, a, b) asm("fma.rn.f32x2 %0, %1, %2, %0;" : "+l"(d) : "l"(a), "l"(b))

// ---------------- Precompute: g_ptab = emb_table @ [conv_w | cross_w] ----------------
__global__ void __launch_bounds__(128) ptab_kernel(
    const float* __restrict__ emb,
    const float* __restrict__ conv_w,
    const float* __restrict__ cross_w)
{
    __shared__ float wt[20][132];
    const int t = threadIdx.x;
    for (int i = t; i < 20 * 128; i += 128) {
        int j = i >> 7, d = i & 127;
        wt[j][d] = (j < 10) ? conv_w[d * 10 + j] : cross_w[d * 10 + (j - 10)];
    }
    __syncthreads();
    int v = blockIdx.x * 128 + t;
    if (v >= VOCAB) return;

    ull acc[20];
#pragma unroll
    for (int j = 0; j < 20; j++) acc[j] = 0ull;
    const float4* ep = reinterpret_cast<const float4*>(emb + (size_t)v * 128);
#pragma unroll 4
    for (int c4 = 0; c4 < 32; c4++) {
        float4 e = ep[c4];
        ull e01 = pk2(e.x, e.y), e23 = pk2(e.z, e.w);
#pragma unroll
        for (int j = 0; j < 20; j++) {
            float4 w = *reinterpret_cast<const float4*>(&wt[j][c4 * 4]);
            FMA2(acc[j], e01, pk2(w.x, w.y));
            FMA2(acc[j], e23, pk2(w.z, w.w));
        }
    }
    float o[20];
#pragma unroll
    for (int j = 0; j < 20; j++) o[j] = unpk_sum(acc[j]);
    float4* op = reinterpret_cast<float4*>(g_ptab + (size_t)v * 20);
#pragma unroll
    for (int k = 0; k < 5; k++)
        op[k] = make_float4(o[k * 4], o[k * 4 + 1], o[k * 4 + 2], o[k * 4 + 3]);
}

// ---------------- Main per-item kernel ----------------
struct Smem {
    union {
        float attn[NN][51];            // 2550 floats (phases 0-3)
        float h2[2][NN][21];           // 2100 floats (phase 3 write / phase 4)
    } u;
    float _padA[2];
    float convp[2][NN][12];            // conv proj rows (12-float stride, 16B aligned)
    float crossp[2][NN][12];           // cross proj rows
    float assign[NN][10];
    float mpw1p[11][20];
    float mpw2p[20][20];
    float mpb1[20], mpb2[20], convb[12];
    float dinv[2][NN];
    float gmax[2][20];
    float pmax[3][2][20];
    float feat[80];
    float zz[2][40];
    int   cnt[2][52];                  // per-dst incoming-edge histogram
    int   start[2][52];                // exclusive prefix (start[g][NN] = E)
    int   cur[2][52];                  // scatter cursors
    unsigned short srcsorted[2][EMAXE];// src ids sorted by dst
};

__global__ void __launch_bounds__(TPB, 8) gmn_kernel(
    const int* __restrict__ utok, const int* __restrict__ rtok,
    const int* __restrict__ uadj, const int* __restrict__ radj,
    const float* __restrict__ attn,
    const float* __restrict__ assignw, const float* __restrict__ conv_b,
    const float* __restrict__ mpw1, const float* __restrict__ mpb1,
    const float* __restrict__ mpw2, const float* __restrict__ mpb2,
    const float* __restrict__ fw1, const float* __restrict__ fb1,
    const float* __restrict__ fw2, const float* __restrict__ fb2,
    float* __restrict__ out, int E)
{
    extern __shared__ char smraw[];
    Smem& s = *reinterpret_cast<Smem*>(smraw);
    const int t = threadIdx.x;
    const int b = blockIdx.x;

    // ---------------- Phase 0: cooperative loads + histogram init ----------------
    for (int i = t; i < NN * NN; i += TPB) s.u.attn[i / NN][i % NN] = attn[i];
    for (int i = t; i < NN * 10; i += TPB) s.assign[i / 10][i % 10] = assignw[i];
    for (int i = t; i < 11 * 20; i += TPB) s.mpw1p[i / 20][i % 20] = mpw1[i];
    for (int i = t; i < 20 * 20; i += TPB) s.mpw2p[i / 20][i % 20] = mpw2[i];
    if (t < 20) { s.mpb1[t] = mpb1[t]; s.mpb2[t] = mpb2[t]; }
    if (t < 12) s.convb[t] = (t < 10) ? conv_b[t] : 0.0f;
    if (t < 104) reinterpret_cast<int*>(&s.cnt[0][0])[t] = 0;
    __syncthreads();

    // ---------------- Phase 0b: histogram (gmem dst reads) + ptab gather ----------------
    for (int i = t; i < 2 * E; i += TPB) {
        int g = i / E, e = i - g * E;
        const int* adj = (g == 0 ? uadj : radj) + (size_t)b * 2 * E;
        atomicAdd(&s.cnt[g][adj[E + e]], 1);
    }
    if (t < 100) {
        int g = t / NN, r = t - (t / NN) * NN;
        int tokv = (g == 0 ? utok : rtok)[b * NN + r];
        const float4* tb = reinterpret_cast<const float4*>(g_ptab + (size_t)tokv * 20);
        float4 v0 = tb[0], v1 = tb[1], v2 = tb[2], v3 = tb[3], v4 = tb[4];
        float4* cp = reinterpret_cast<float4*>(&s.convp[g][r][0]);
        cp[0] = v0;
        cp[1] = v1;
        cp[2] = make_float4(v2.x, v2.y, 0.f, 0.f);
        float4* xp = reinterpret_cast<float4*>(&s.crossp[g][r][0]);
        xp[0] = make_float4(v2.z, v2.w, v3.x, v3.y);
        xp[1] = make_float4(v3.z, v3.w, v4.x, v4.y);
        xp[2] = make_float4(v4.z, v4.w, 0.f, 0.f);
    }
    __syncthreads();

    // ---------------- Phase 1: prefix scan (2 threads) + dinv from histogram ----------------
    if (t < 2) {
        int acc = 0;
        for (int n = 0; n < NN; n++) {
            s.start[t][n] = acc;
            s.cur[t][n] = acc;
            acc += s.cnt[t][n];
        }
        s.start[t][NN] = acc;
    } else if (t < 102) {
        int idx = t - 2;
        int g = idx / NN, n = idx - g * NN;
        s.dinv[g][n] = rsqrtf((float)(s.cnt[g][n] + 1));
    }
    __syncthreads();

    // ---------------- Phase 2: scatter edges sorted by dst (gmem re-read, L2-hot) ----------------
    for (int i = t; i < 2 * E; i += TPB) {
        int g = i / E, e = i - g * E;
        const int* adj = (g == 0 ? uadj : radj) + (size_t)b * 2 * E;
        int sr = adj[e], ds = adj[E + e];
        int pos = atomicAdd(&s.cur[g][ds], 1);
        s.srcsorted[g][pos] = (unsigned short)sr;
    }
    __syncthreads();

    // ---------------- Phase 3: gather GCN + cross matvec + cosine + MLPs ----------------
    float h2f[20];
    const int g3 = (t < 100) ? (t / NN) : 0;
    const int n3 = (t < 100) ? (t - g3 * NN) : 0;
    if (t < 100) {
        float dn = s.dinv[g3][n3];
        float d2 = dn * dn;
        // self-loop + bias seed (packed)
        ull sva[5];
        {
            ull d2p = pk2(d2, d2);
            const ull* cb2 = reinterpret_cast<const ull*>(&s.convb[0]);
            const ull* cself = reinterpret_cast<const ull*>(&s.convp[g3][n3][0]);
#pragma unroll
            for (int p = 0; p < 5; p++) { sva[p] = cb2[p]; FMA2(sva[p], d2p, cself[p]); }
        }
        // incoming-edge gather (atomic-free)
        int e0 = s.start[g3][n3], e1 = s.start[g3][n3 + 1];
        for (int i = e0; i < e1; i++) {
            int sr = s.srcsorted[g3][i];
            float norm = dn * s.dinv[g3][sr];
            ull np = pk2(norm, norm);
            const ulonglong2* cr = reinterpret_cast<const ulonglong2*>(&s.convp[g3][sr][0]);
            ulonglong2 C0 = cr[0], C1 = cr[1];
            ull C4 = *reinterpret_cast<const ull*>(&s.convp[g3][sr][8]);
            FMA2(sva[0], np, C0.x); FMA2(sva[1], np, C0.y);
            FMA2(sva[2], np, C1.x); FMA2(sva[3], np, C1.y);
            FMA2(sva[4], np, C4);
        }
        float sv[10];
#pragma unroll
        for (int p = 0; p < 5; p++) {
            float2 f = unpk(sva[p]);
            sv[p * 2] = f.x; sv[p * 2 + 1] = f.y;
        }

        // cross matvec: cv = attn[n3,:] @ crossp[other]
        ull cacc[5];
#pragma unroll
        for (int p = 0; p < 5; p++) cacc[p] = 0ull;
        const float* Arow = &s.u.attn[n3][0];
        const float* cbase = &s.crossp[1 - g3][0][0];
#pragma unroll 5
        for (int m = 0; m < NN; m++) {
            float Av = Arow[m];
            ull av2 = pk2(Av, Av);
            const ulonglong2* cr = reinterpret_cast<const ulonglong2*>(cbase + m * 12);
            ulonglong2 L0 = cr[0], L1 = cr[1];
            ull L4 = *reinterpret_cast<const ull*>(cbase + m * 12 + 8);
            FMA2(cacc[0], av2, L0.x); FMA2(cacc[1], av2, L0.y);
            FMA2(cacc[2], av2, L1.x); FMA2(cacc[3], av2, L1.y);
            FMA2(cacc[4], av2, L4);
        }
        float cv[10];
#pragma unroll
        for (int p = 0; p < 5; p++) {
            float2 f = unpk(cacc[p]);
            cv[p * 2] = f.x; cv[p * 2 + 1] = f.y;
        }

        // cosine with assign weighting
        float dot = 0.0f, na = 0.0f, nc = 0.0f;
#pragma unroll
        for (int j = 0; j < 10; j++) {
            float aw = s.assign[n3][j];
            float av = aw * sv[j], cw2 = aw * cv[j];
            dot += av * cw2; na += av * av; nc += cw2 * cw2;
        }
        na = fmaxf(sqrtf(na), EPSV);
        nc = fmaxf(sqrtf(nc), EPSV);
        float dist = dot / (na * nc);

        // MLP layer 1 (packed)
        ull aa[10];
        {
            const ull* bb = reinterpret_cast<const ull*>(&s.mpb1[0]);
            const ull* w0 = reinterpret_cast<const ull*>(&s.mpw1p[0][0]);
            ull dd = pk2(dist, dist);
#pragma unroll
            for (int p = 0; p < 10; p++) { aa[p] = bb[p]; FMA2(aa[p], dd, w0[p]); }
#pragma unroll
            for (int k = 0; k < 10; k++) {
                ull xx = pk2(sv[k], sv[k]);
                const ulonglong2* wr = reinterpret_cast<const ulonglong2*>(&s.mpw1p[k + 1][0]);
                ulonglong2 W0 = wr[0], W1 = wr[1], W2 = wr[2], W3 = wr[3], W4 = wr[4];
                FMA2(aa[0], xx, W0.x); FMA2(aa[1], xx, W0.y);
                FMA2(aa[2], xx, W1.x); FMA2(aa[3], xx, W1.y);
                FMA2(aa[4], xx, W2.x); FMA2(aa[5], xx, W2.y);
                FMA2(aa[6], xx, W3.x); FMA2(aa[7], xx, W3.y);
                FMA2(aa[8], xx, W4.x); FMA2(aa[9], xx, W4.y);
            }
        }
        float h1f[20];
#pragma unroll
        for (int p = 0; p < 10; p++) {
            float2 f = unpk(aa[p]);
            h1f[p * 2] = fmaxf(f.x, 0.0f);
            h1f[p * 2 + 1] = fmaxf(f.y, 0.0f);
        }

        // MLP layer 2 (packed)
        ull hh[10];
        {
            const ull* bb = reinterpret_cast<const ull*>(&s.mpb2[0]);
#pragma unroll
            for (int p = 0; p < 10; p++) hh[p] = bb[p];
#pragma unroll
            for (int k = 0; k < 20; k++) {
                ull xx = pk2(h1f[k], h1f[k]);
                const ulonglong2* wr = reinterpret_cast<const ulonglong2*>(&s.mpw2p[k][0]);
                ulonglong2 W0 = wr[0], W1 = wr[1], W2 = wr[2], W3 = wr[3], W4 = wr[4];
                FMA2(hh[0], xx, W0.x); FMA2(hh[1], xx, W0.y);
                FMA2(hh[2], xx, W1.x); FMA2(hh[3], xx, W1.y);
                FMA2(hh[4], xx, W2.x); FMA2(hh[5], xx, W2.y);
                FMA2(hh[6], xx, W3.x); FMA2(hh[7], xx, W3.y);
                FMA2(hh[8], xx, W4.x); FMA2(hh[9], xx, W4.y);
            }
        }
#pragma unroll
        for (int p = 0; p < 10; p++) {
            float2 f = unpk(hh[p]);
            h2f[p * 2] = f.x; h2f[p * 2 + 1] = f.y;
        }
    }
    __syncthreads();   // attn reads done before h2 overwrites the union
    if (t < 100) {
#pragma unroll
        for (int j = 0; j < 20; j++) s.u.h2[g3][n3][j] = h2f[j];
    }
    __syncthreads();

    // ---------------- Phase 4: node-max (3-way), features, FFN, sigmoid ----------------
    if (t < 120) {
        int q = t / 40, r = t - q * 40;
        int g = r / 20, j = r - g * 20;
        int n0 = q * 17, n1 = (q == 2) ? NN : (q + 1) * 17;
        float m = -3.4e38f;
        for (int n = n0; n < n1; n++) m = fmaxf(m, s.u.h2[g][n][j]);
        s.pmax[q][g][j] = m;
    }
    __syncthreads();
    if (t < 40) {
        int g = t / 20, j = t - g * 20;
        s.gmax[g][j] = fmaxf(s.pmax[0][g][j], fmaxf(s.pmax[1][g][j], s.pmax[2][g][j]));
    }
    __syncthreads();
    if (t < 80) {
        int q = t / 20, i = t - q * 20;
        float gu = s.gmax[0][i], gr = s.gmax[1][i];
        s.feat[t] = (q == 0) ? gu : (q == 1) ? gr : (q == 2) ? gu * gr : fabsf(gu - gr);
    }
    __syncthreads();
    if (t < 80) {
        int half = t / 40, o = t - half * 40;
        float acc2 = half ? 0.0f : fb1[o];
        for (int i = half * 40; i < half * 40 + 40; i++)
            acc2 += s.feat[i] * fw1[i * 40 + o];
        s.zz[half][o] = acc2;
    }
    __syncthreads();
    if (t == 0) {
        float lg = fb2[0];
        for (int i = 0; i < 40; i++) {
            float z = fmaxf(s.zz[0][i] + s.zz[1][i], 0.0f);
            lg += z * fw2[i];
        }
        out[b] = 1.0f / (1.0f + expf(-lg));
    }
}

extern "C" void kernel_launch(void* const* d_in, const int* in_sizes, int n_in,
                              void* d_out, int out_size) {
    const int* utok   = (const int*)d_in[0];
    const int* rtok   = (const int*)d_in[1];
    const int* uadj   = (const int*)d_in[2];
    const int* radj   = (const int*)d_in[3];
    const float* emb  = (const float*)d_in[4];
    const float* cw   = (const float*)d_in[5];
    const float* cb   = (const float*)d_in[6];
    const float* xw   = (const float*)d_in[7];
    const float* attn = (const float*)d_in[8];
    const float* asw  = (const float*)d_in[9];
    const float* mw1  = (const float*)d_in[10];
    const float* mb1  = (const float*)d_in[11];
    const float* mw2  = (const float*)d_in[12];
    const float* mb2  = (const float*)d_in[13];
    const float* fw1  = (const float*)d_in[14];
    const float* fb1  = (const float*)d_in[15];
    const float* fw2  = (const float*)d_in[16];
    const float* fb2  = (const float*)d_in[17];
    float* out = (float*)d_out;

    int B = in_sizes[0] / NN;
    int E = in_sizes[2] / (2 * B);

    ptab_kernel<<<(VOCAB + 127) / 128, 128>>>(emb, cw, xw);

    cudaFuncSetAttribute(gmn_kernel, cudaFuncAttributeMaxDynamicSharedMemorySize,
                         (int)sizeof(Smem));
    gmn_kernel<<<B, TPB, sizeof(Smem)>>>(utok, rtok, uadj, radj,
                                         attn, asw, cb,
                                         mw1, mb1, mw2, mb2,
                                         fw1, fb1, fw2, fb2,
                                         out, E);
}

// round 7
// speedup vs baseline: 3.2920x; 1.0525x over previous
#include <cuda_runtime.h>

#define NN 50
#define TPB 256
#define IPB 2
#define EPSV 1e-8f
#define EMAXE 256
#define VOCAB 21128

typedef unsigned long long ull;

// Precomputed projected embedding table: row v = [emb[v]@conv_w (10) | emb[v]@cross_w (10)]
__device__ float g_ptab[VOCAB * 20];

__device__ __forceinline__ ull pk2(float a, float b) {
    union { float2 f; ull u; } c;
    c.f = make_float2(a, b);
    return c.u;
}
__device__ __forceinline__ float2 unpk(ull u) {
    union { float2 f; ull u; } c;
    c.u = u;
    return c.f;
}
__device__ __forceinline__ float unpk_sum(ull u) {
    float2 f = unpk(u);
    return f.x + f.y;
}
#define FMA2(d, a, b) asm("fma.rn.f32x2 %0, %1, %2, %0;" : "+l"(d) : "l"(a), "l"(b))

// ---------------- Precompute: g_ptab = emb_table @ [conv_w | cross_w] ----------------
__global__ void __launch_bounds__(128) ptab_kernel(
    const float* __restrict__ emb,
    const float* __restrict__ conv_w,
    const float* __restrict__ cross_w)
{
    __shared__ float wt[20][132];
    const int t = threadIdx.x;
    for (int i = t; i < 20 * 128; i += 128) {
        int j = i >> 7, d = i & 127;
        wt[j][d] = (j < 10) ? conv_w[d * 10 + j] : cross_w[d * 10 + (j - 10)];
    }
    __syncthreads();
    int v = blockIdx.x * 128 + t;
    if (v >= VOCAB) return;

    ull acc[20];
#pragma unroll
    for (int j = 0; j < 20; j++) acc[j] = 0ull;
    const float4* ep = reinterpret_cast<const float4*>(emb + (size_t)v * 128);
#pragma unroll 4
    for (int c4 = 0; c4 < 32; c4++) {
        float4 e = ep[c4];
        ull e01 = pk2(e.x, e.y), e23 = pk2(e.z, e.w);
#pragma unroll
        for (int j = 0; j < 20; j++) {
            float4 w = *reinterpret_cast<const float4*>(&wt[j][c4 * 4]);
            FMA2(acc[j], e01, pk2(w.x, w.y));
            FMA2(acc[j], e23, pk2(w.z, w.w));
        }
    }
    float o[20];
#pragma unroll
    for (int j = 0; j < 20; j++) o[j] = unpk_sum(acc[j]);
    float4* op = reinterpret_cast<float4*>(g_ptab + (size_t)v * 20);
#pragma unroll
    for (int k = 0; k < 5; k++)
        op[k] = make_float4(o[k * 4], o[k * 4 + 1], o[k * 4 + 2], o[k * 4 + 3]);
}

// ---------------- Main kernel: 2 items per CTA ----------------
struct PerItem {
    union {
        struct { float convp[2][NN][12]; float crossp[2][NN][12]; } cc; // 2400 f
        float h2[2][NN][21];                                            // 2100 f
    } u;
    float dinv[2][NN];
    float gmax[2][20];
    float pmax[3][2][20];
    float feat[80];
    float zz[2][40];
    int   cnt[2][52];                  // histogram, then scatter cursor
    int   start[2][52];                // exclusive prefix (start[g][NN] = E)
    unsigned short srcsorted[2][EMAXE];
};

struct Smem {
    float attn[NN][51];                // shared constants (loaded once per CTA)
    float _p0[2];
    float assign[NN][10];
    float mpw1p[11][20];
    float mpw2p[20][20];
    float mpb1[20], mpb2[20], convb[12];
    PerItem it[IPB];
};

__global__ void __launch_bounds__(TPB, 4) gmn_kernel(
    const int* __restrict__ utok, const int* __restrict__ rtok,
    const int* __restrict__ uadj, const int* __restrict__ radj,
    const float* __restrict__ attn,
    const float* __restrict__ assignw, const float* __restrict__ conv_b,
    const float* __restrict__ mpw1, const float* __restrict__ mpb1,
    const float* __restrict__ mpw2, const float* __restrict__ mpb2,
    const float* __restrict__ fw1, const float* __restrict__ fb1,
    const float* __restrict__ fw2, const float* __restrict__ fb2,
    float* __restrict__ out, int E)
{
    extern __shared__ char smraw[];
    Smem& s = *reinterpret_cast<Smem*>(smraw);
    const int t = threadIdx.x;
    const int tt = t & 127;            // per-item thread id
    const int p = t >> 7;              // item slot 0/1
    const int item = blockIdx.x * IPB + p;

    // ---------------- Phase 0: shared constants (256 threads) + per-item init ----------------
    for (int i = t; i < NN * NN; i += TPB) s.attn[i / NN][i % NN] = attn[i];
    for (int i = t; i < NN * 10; i += TPB) s.assign[i / 10][i % 10] = assignw[i];
    for (int i = t; i < 11 * 20; i += TPB) s.mpw1p[i / 20][i % 20] = mpw1[i];
    for (int i = t; i < 20 * 20; i += TPB) s.mpw2p[i / 20][i % 20] = mpw2[i];
    if (t < 20) { s.mpb1[t] = mpb1[t]; s.mpb2[t] = mpb2[t]; }
    if (t < 12) s.convb[t] = (t < 10) ? conv_b[t] : 0.0f;
    if (tt < 104) reinterpret_cast<int*>(&s.it[p].cnt[0][0])[tt] = 0;
    __syncthreads();

    // ---------------- Phase 0b: histogram (gmem dst reads) + ptab gather ----------------
    for (int i = tt; i < 2 * E; i += 128) {
        int g = i / E, e = i - g * E;
        const int* adj = (g == 0 ? uadj : radj) + (size_t)item * 2 * E;
        atomicAdd(&s.it[p].cnt[g][adj[E + e]], 1);
    }
    if (tt < 100) {
        int g = tt / NN, r = tt - (tt / NN) * NN;
        int tokv = (g == 0 ? utok : rtok)[item * NN + r];
        const float4* tb = reinterpret_cast<const float4*>(g_ptab + (size_t)tokv * 20);
        float4 v0 = tb[0], v1 = tb[1], v2 = tb[2], v3 = tb[3], v4 = tb[4];
        float4* cp = reinterpret_cast<float4*>(&s.it[p].u.cc.convp[g][r][0]);
        cp[0] = v0;
        cp[1] = v1;
        cp[2] = make_float4(v2.x, v2.y, 0.f, 0.f);
        float4* xp = reinterpret_cast<float4*>(&s.it[p].u.cc.crossp[g][r][0]);
        xp[0] = make_float4(v2.z, v2.w, v3.x, v3.y);
        xp[1] = make_float4(v3.z, v3.w, v4.x, v4.y);
        xp[2] = make_float4(v4.z, v4.w, 0.f, 0.f);
    }
    __syncthreads();

    // ---------------- Phase 1: warp-parallel prefix scan + dinv ----------------
    {
        const int lane = t & 31;
        const int w = t >> 5;                 // warps 0,1 item0 g0/g1; warps 4,5 item1
        if ((w & 2) == 0 && lane < 25) {
            const int p2 = w >> 2, g2 = w & 1;
            int c0 = s.it[p2].cnt[g2][2 * lane];
            int c1 = s.it[p2].cnt[g2][2 * lane + 1];
            s.it[p2].dinv[g2][2 * lane]     = rsqrtf((float)(c0 + 1));
            s.it[p2].dinv[g2][2 * lane + 1] = rsqrtf((float)(c1 + 1));
            int pair = c0 + c1;
            int incl = pair;
#pragma unroll
            for (int off = 1; off < 32; off <<= 1) {
                int v = __shfl_up_sync(0x1ffffffu, incl, off);
                if (lane >= off) incl += v;
            }
            int excl = incl - pair;
            s.it[p2].start[g2][2 * lane] = excl;
            s.it[p2].start[g2][2 * lane + 1] = excl + c0;
            s.it[p2].cnt[g2][2 * lane] = excl;          // cursor
            s.it[p2].cnt[g2][2 * lane + 1] = excl + c0; // cursor
            if (lane == 24) s.it[p2].start[g2][NN] = incl;
        }
    }
    __syncthreads();

    // ---------------- Phase 2: scatter edges sorted by dst (gmem re-read, L2-hot) ----------------
    for (int i = tt; i < 2 * E; i += 128) {
        int g = i / E, e = i - g * E;
        const int* adj = (g == 0 ? uadj : radj) + (size_t)item * 2 * E;
        int sr = adj[e], ds = adj[E + e];
        int pos = atomicAdd(&s.it[p].cnt[g][ds], 1);
        s.it[p].srcsorted[g][pos] = (unsigned short)sr;
    }
    __syncthreads();

    // ---------------- Phase 3: gather GCN + cross matvec + cosine + MLPs ----------------
    float h2f[20];
    const int g3 = (tt < 100) ? (tt / NN) : 0;
    const int n3 = (tt < 100) ? (tt - g3 * NN) : 0;
    if (tt < 100) {
        PerItem& pi = s.it[p];
        float dn = pi.dinv[g3][n3];
        float d2 = dn * dn;
        ull sva[5];
        {
            ull d2p = pk2(d2, d2);
            const ull* cb2 = reinterpret_cast<const ull*>(&s.convb[0]);
            const ull* cself = reinterpret_cast<const ull*>(&pi.u.cc.convp[g3][n3][0]);
#pragma unroll
            for (int q = 0; q < 5; q++) { sva[q] = cb2[q]; FMA2(sva[q], d2p, cself[q]); }
        }
        int e0 = pi.start[g3][n3], e1 = pi.start[g3][n3 + 1];
        for (int i = e0; i < e1; i++) {
            int sr = pi.srcsorted[g3][i];
            float norm = dn * pi.dinv[g3][sr];
            ull np = pk2(norm, norm);
            const ulonglong2* cr = reinterpret_cast<const ulonglong2*>(&pi.u.cc.convp[g3][sr][0]);
            ulonglong2 C0 = cr[0], C1 = cr[1];
            ull C4 = *reinterpret_cast<const ull*>(&pi.u.cc.convp[g3][sr][8]);
            FMA2(sva[0], np, C0.x); FMA2(sva[1], np, C0.y);
            FMA2(sva[2], np, C1.x); FMA2(sva[3], np, C1.y);
            FMA2(sva[4], np, C4);
        }
        float sv[10];
#pragma unroll
        for (int q = 0; q < 5; q++) {
            float2 f = unpk(sva[q]);
            sv[q * 2] = f.x; sv[q * 2 + 1] = f.y;
        }

        // cross matvec: cv = attn[n3,:] @ crossp[other]
        ull cacc[5];
#pragma unroll
        for (int q = 0; q < 5; q++) cacc[q] = 0ull;
        const float* Arow = &s.attn[n3][0];
        const float* cbase = &pi.u.cc.crossp[1 - g3][0][0];
#pragma unroll 5
        for (int m = 0; m < NN; m++) {
            float Av = Arow[m];
            ull av2 = pk2(Av, Av);
            const ulonglong2* cr = reinterpret_cast<const ulonglong2*>(cbase + m * 12);
            ulonglong2 L0 = cr[0], L1 = cr[1];
            ull L4 = *reinterpret_cast<const ull*>(cbase + m * 12 + 8);
            FMA2(cacc[0], av2, L0.x); FMA2(cacc[1], av2, L0.y);
            FMA2(cacc[2], av2, L1.x); FMA2(cacc[3], av2, L1.y);
            FMA2(cacc[4], av2, L4);
        }
        float cv[10];
#pragma unroll
        for (int q = 0; q < 5; q++) {
            float2 f = unpk(cacc[q]);
            cv[q * 2] = f.x; cv[q * 2 + 1] = f.y;
        }

        // cosine with assign weighting
        float dot = 0.0f, na = 0.0f, nc = 0.0f;
#pragma unroll
        for (int j = 0; j < 10; j++) {
            float aw = s.assign[n3][j];
            float av = aw * sv[j], cw2 = aw * cv[j];
            dot += av * cw2; na += av * av; nc += cw2 * cw2;
        }
        na = fmaxf(sqrtf(na), EPSV);
        nc = fmaxf(sqrtf(nc), EPSV);
        float dist = dot / (na * nc);

        // MLP layer 1 (packed)
        ull aa[10];
        {
            const ull* bb = reinterpret_cast<const ull*>(&s.mpb1[0]);
            const ull* w0 = reinterpret_cast<const ull*>(&s.mpw1p[0][0]);
            ull dd = pk2(dist, dist);
#pragma unroll
            for (int q = 0; q < 10; q++) { aa[q] = bb[q]; FMA2(aa[q], dd, w0[q]); }
#pragma unroll
            for (int k = 0; k < 10; k++) {
                ull xx = pk2(sv[k], sv[k]);
                const ulonglong2* wr = reinterpret_cast<const ulonglong2*>(&s.mpw1p[k + 1][0]);
                ulonglong2 W0 = wr[0], W1 = wr[1], W2 = wr[2], W3 = wr[3], W4 = wr[4];
                FMA2(aa[0], xx, W0.x); FMA2(aa[1], xx, W0.y);
                FMA2(aa[2], xx, W1.x); FMA2(aa[3], xx, W1.y);
                FMA2(aa[4], xx, W2.x); FMA2(aa[5], xx, W2.y);
                FMA2(aa[6], xx, W3.x); FMA2(aa[7], xx, W3.y);
                FMA2(aa[8], xx, W4.x); FMA2(aa[9], xx, W4.y);
            }
        }
        float h1f[20];
#pragma unroll
        for (int q = 0; q < 10; q++) {
            float2 f = unpk(aa[q]);
            h1f[q * 2] = fmaxf(f.x, 0.0f);
            h1f[q * 2 + 1] = fmaxf(f.y, 0.0f);
        }

        // MLP layer 2 (packed)
        ull hh[10];
        {
            const ull* bb = reinterpret_cast<const ull*>(&s.mpb2[0]);
#pragma unroll
            for (int q = 0; q < 10; q++) hh[q] = bb[q];
#pragma unroll
            for (int k = 0; k < 20; k++) {
                ull xx = pk2(h1f[k], h1f[k]);
                const ulonglong2* wr = reinterpret_cast<const ulonglong2*>(&s.mpw2p[k][0]);
                ulonglong2 W0 = wr[0], W1 = wr[1], W2 = wr[2], W3 = wr[3], W4 = wr[4];
                FMA2(hh[0], xx, W0.x); FMA2(hh[1], xx, W0.y);
                FMA2(hh[2], xx, W1.x); FMA2(hh[3], xx, W1.y);
                FMA2(hh[4], xx, W2.x); FMA2(hh[5], xx, W2.y);
                FMA2(hh[6], xx, W3.x); FMA2(hh[7], xx, W3.y);
                FMA2(hh[8], xx, W4.x); FMA2(hh[9], xx, W4.y);
            }
        }
#pragma unroll
        for (int q = 0; q < 10; q++) {
            float2 f = unpk(hh[q]);
            h2f[q * 2] = f.x; h2f[q * 2 + 1] = f.y;
        }
    }
    __syncthreads();   // convp/crossp reads done before h2 overwrites the union
    if (tt < 100) {
#pragma unroll
        for (int j = 0; j < 20; j++) s.it[p].u.h2[g3][n3][j] = h2f[j];
    }
    __syncthreads();

    // ---------------- Phase 4: node-max (3-way), features, FFN, sigmoid ----------------
    PerItem& pi = s.it[p];
    if (tt < 120) {
        int q = tt / 40, r = tt - q * 40;
        int g = r / 20, j = r - g * 20;
        int n0 = q * 17, n1 = (q == 2) ? NN : (q + 1) * 17;
        float m = -3.4e38f;
        for (int n = n0; n < n1; n++) m = fmaxf(m, pi.u.h2[g][n][j]);
        pi.pmax[q][g][j] = m;
    }
    __syncthreads();
    if (tt < 40) {
        int g = tt / 20, j = tt - g * 20;
        pi.gmax[g][j] = fmaxf(pi.pmax[0][g][j], fmaxf(pi.pmax[1][g][j], pi.pmax[2][g][j]));
    }
    __syncthreads();
    if (tt < 80) {
        int q = tt / 20, i = tt - q * 20;
        float gu = pi.gmax[0][i], gr = pi.gmax[1][i];
        pi.feat[tt] = (q == 0) ? gu : (q == 1) ? gr : (q == 2) ? gu * gr : fabsf(gu - gr);
    }
    __syncthreads();
    if (tt < 80) {
        int half = tt / 40, o = tt - half * 40;
        float acc2 = half ? 0.0f : fb1[o];
        for (int i = half * 40; i < half * 40 + 40; i++)
            acc2 += pi.feat[i] * fw1[i * 40 + o];
        pi.zz[half][o] = acc2;
    }
    __syncthreads();
    if (tt == 0) {
        float lg = fb2[0];
        for (int i = 0; i < 40; i++) {
            float z = fmaxf(pi.zz[0][i] + pi.zz[1][i], 0.0f);
            lg += z * fw2[i];
        }
        out[item] = 1.0f / (1.0f + expf(-lg));
    }
}

extern "C" void kernel_launch(void* const* d_in, const int* in_sizes, int n_in,
                              void* d_out, int out_size) {
    const int* utok   = (const int*)d_in[0];
    const int* rtok   = (const int*)d_in[1];
    const int* uadj   = (const int*)d_in[2];
    const int* radj   = (const int*)d_in[3];
    const float* emb  = (const float*)d_in[4];
    const float* cw   = (const float*)d_in[5];
    const float* cb   = (const float*)d_in[6];
    const float* xw   = (const float*)d_in[7];
    const float* attn = (const float*)d_in[8];
    const float* asw  = (const float*)d_in[9];
    const float* mw1  = (const float*)d_in[10];
    const float* mb1  = (const float*)d_in[11];
    const float* mw2  = (const float*)d_in[12];
    const float* mb2  = (const float*)d_in[13];
    const float* fw1  = (const float*)d_in[14];
    const float* fb1  = (const float*)d_in[15];
    const float* fw2  = (const float*)d_in[16];
    const float* fb2  = (const float*)d_in[17];
    float* out = (float*)d_out;

    int B = in_sizes[0] / NN;
    int E = in_sizes[2] / (2 * B);

    ptab_kernel<<<(VOCAB + 127) / 128, 128>>>(emb, cw, xw);

    cudaFuncSetAttribute(gmn_kernel, cudaFuncAttributeMaxDynamicSharedMemorySize,
                         (int)sizeof(Smem));
    gmn_kernel<<<B / IPB, TPB, sizeof(Smem)>>>(utok, rtok, uadj, radj,
                                               attn, asw, cb,
                                               mw1, mb1, mw2, mb2,
                                               fw1, fb1, fw2, fb2,
                                               out, E);
}